// round 7
// baseline (speedup 1.0000x reference)
#include <cuda_runtime.h>
#include <cstdint>

#define KCAP 8
#define NKP 15
#define OC 64
#define XD 12
#define NMOM 91            // cnt(1) + Sx(12) + Sxx upper-tri(78)
#define SENT 0x7FFFFFFF
#define VMAX 65536
#define NSLOT_TOT ((65536 + 16384 + 4096 + 1024) * KCAP)   // 696320

// ---------------- device scratch (static, no allocs) ----------------
__device__ int    g_slots[NSLOT_TOT];       // per-scale regions, K smallest point idx per voxel
__device__ float  g_cent[VMAX * 3];
__device__ int    g_npts[VMAX];
__device__ int    g_active[VMAX];
__device__ int    g_nactive[4];
__device__ double g_mom[4 * 92];            // per scale: [0]=cnt, [1..12]=Sx, [13..90]=Sxx
__device__ float  g_ym[OC];
__device__ float  g_apre[OC];
__device__ double g_S1[OC];
__device__ double g_S2[OC * OC];
__device__ float  g_out[(size_t)VMAX * OC]; // per-active-voxel KP-conv output
__device__ float  g_pmean[OC], g_palpha[OC], g_fill[OC];

// ---------------- kernel 1: init all scratch once ----------------
__global__ void k_init() {
    int i = blockIdx.x * blockDim.x + threadIdx.x;
    if (i < NSLOT_TOT) g_slots[i] = SENT;
    if (i < 4 * 92) g_mom[i] = 0.0;
    if (i < 4) g_nactive[i] = 0;
}

// ---------------- kernel 2: fused 4-scale insert (first-K by original index) ----------------
__global__ void k_insert(const float* __restrict__ pts, int N) {
    int i = blockIdx.x * blockDim.x + threadIdx.x;
    if (i >= N) return;
    float x = pts[i * 5 + 0], y = pts[i * 5 + 1], z = pts[i * 5 + 2];
    if (!(z >= -5.0f && z < 3.0f)) return;
    float bx = x + 51.2f, by = y + 51.2f;
    int sbase = 0, G = 256;
    float vs = 0.4f;
    #pragma unroll
    for (int s = 0; s < 4; s++) {
        float fx = floorf(bx / vs), fy = floorf(by / vs);
        if (fx >= 0.f && fy >= 0.f && fx < (float)G && fy < (float)G) {
            int ix = (int)fx, iy = (int)fy;
            int* sl = &g_slots[sbase + (iy * G + ix) * KCAP];
            int val = i;
            #pragma unroll
            for (int k = 0; k < KCAP; k++) {
                int cur = sl[k];            // racy pre-check OK: slot values only decrease
                if (cur < val) continue;    // val belongs strictly deeper
                int old = atomicMin(&sl[k], val);
                if (old == SENT) break;     // placed in empty tail slot
                val = max(val, old);        // carry larger index deeper
            }
        }
        sbase += G * G * KCAP;
        G >>= 1;
        vs *= 2.0f;
    }
}

// ---------------- kernel 3: fused per-voxel centroid + active detect + moments ----------------
// one thread per voxel; 91 register accumulators, one warp reduction amortized over <=8 points
__global__ void __launch_bounds__(256) k_voxstats(
        const float* __restrict__ pts, const float* __restrict__ kp,
        int G, float vs, int sbase, int scale) {
    __shared__ float skp[NKP * 3];
    __shared__ float sAcc[NMOM];
    int t = threadIdx.x, lane = t & 31;
    if (t < NKP * 3) skp[t] = kp[t];
    if (t < NMOM) sAcc[t] = 0.f;
    __syncthreads();

    int v = blockIdx.x * 256 + t;           // V is always a multiple of 256
    const int* sl = &g_slots[sbase + v * KCAP];
    float ax = (float)(v % G) + vs * 0.5f;  // reference's index-space anchor + vs/2
    float ay = (float)(v / G) + vs * 0.5f;

    // pass 1: count / centroid / active
    int idxs[KCAP];
    int cnt = 0;
    float sx = 0.f, sy = 0.f, sz = 0.f;
    bool act = false;
    #pragma unroll
    for (int k = 0; k < KCAP; k++) {
        int idx = sl[k];
        idxs[k] = idx;
        if (idx == SENT) continue;
        float a = __ldg(&pts[idx * 5 + 0]);
        float b = __ldg(&pts[idx * 5 + 1]);
        float c = __ldg(&pts[idx * 5 + 2]);
        sx += a; sy += b; sz += c; cnt++;
        if (!act) {
            float dx = a - ax, dy = b - ay, dz = c - 4.0f;
            #pragma unroll
            for (int q = 0; q < NKP; q++) {
                float ex = dx - skp[q * 3 + 0];
                float ey = dy - skp[q * 3 + 1];
                float ez = dz - skp[q * 3 + 2];
                if (ex * ex + ey * ey + ez * ez < 1.0f) { act = true; break; }
            }
        }
    }
    g_npts[v] = cnt;
    float nf = (float)max(cnt, 1);
    float cx = sx / nf, cy = sy / nf, cz = sz / nf;
    g_cent[v * 3 + 0] = cx;
    g_cent[v * 3 + 1] = cy;
    g_cent[v * 3 + 2] = cz;
    if (act) { int p = atomicAdd(&g_nactive[scale], 1); g_active[p] = v; }

    // pass 2: per-thread moment accumulation (point rows hot in L1)
    float m1[XD];
    float m2[78];
    #pragma unroll
    for (int i2 = 0; i2 < XD; i2++) m1[i2] = 0.f;
    #pragma unroll
    for (int i2 = 0; i2 < 78; i2++) m2[i2] = 0.f;
    float n = (float)cnt;
    #pragma unroll
    for (int k = 0; k < KCAP; k++) {
        int idx = idxs[k];
        if (idx == SENT) continue;
        float a  = __ldg(&pts[idx * 5 + 0]);
        float b  = __ldg(&pts[idx * 5 + 1]);
        float c  = __ldg(&pts[idx * 5 + 2]);
        float f0 = __ldg(&pts[idx * 5 + 3]);
        float f1 = __ldg(&pts[idx * 5 + 4]);
        float x[XD];
        x[0] = f0; x[1] = f1;
        x[2] = a - ax; x[3] = b - ay; x[4] = c - 4.0f;
        x[5] = a - cx; x[6] = b - cy; x[7] = c - cz;
        x[8] = cx; x[9] = cy; x[10] = cz; x[11] = n;
        #pragma unroll
        for (int i2 = 0; i2 < XD; i2++) m1[i2] += x[i2];
        int j = 0;
        #pragma unroll
        for (int a2 = 0; a2 < XD; a2++)
            #pragma unroll
            for (int b2 = a2; b2 < XD; b2++) { m2[j] += x[a2] * x[b2]; j++; }
    }

    // warp butterfly reductions, lane0 -> shared atomics, then block -> global (double)
    {
        float val = (float)cnt;
        #pragma unroll
        for (int o = 16; o; o >>= 1) val += __shfl_xor_sync(0xffffffffu, val, o);
        if (lane == 0) atomicAdd(&sAcc[0], val);
    }
    #pragma unroll
    for (int i2 = 0; i2 < XD; i2++) {
        float val = m1[i2];
        #pragma unroll
        for (int o = 16; o; o >>= 1) val += __shfl_xor_sync(0xffffffffu, val, o);
        if (lane == 0) atomicAdd(&sAcc[1 + i2], val);
    }
    #pragma unroll
    for (int i2 = 0; i2 < 78; i2++) {
        float val = m2[i2];
        #pragma unroll
        for (int o = 16; o; o >>= 1) val += __shfl_xor_sync(0xffffffffu, val, o);
        if (lane == 0) atomicAdd(&sAcc[13 + i2], val);
    }
    __syncthreads();
    if (t < NMOM) atomicAdd(&g_mom[scale * 92 + t], (double)sAcc[t]);
}

// ---------------- kernel 4: finalize pre-BN params (exact, closed-form) ----------------
__global__ void k_prebn(const float* __restrict__ w_pre, const float* __restrict__ b_pre,
                        const float* __restrict__ g_pre, int scale) {
    int c = threadIdx.x;
    if (c >= OC) return;
    const double* mom = &g_mom[scale * 92];
    double cnt = mom[0];
    double den = cnt > 1.0 ? cnt : 1.0;
    double wc[XD];
    #pragma unroll
    for (int i = 0; i < XD; i++) wc[i] = (double)w_pre[i * OC + c];
    double sxw = 0;
    #pragma unroll
    for (int i = 0; i < XD; i++) sxw += mom[1 + i] * wc[i];
    double b = (double)b_pre[c];
    double ym = (sxw + cnt * b) / den;
    double q = 0;
    int j = 13;
    for (int a = 0; a < XD; a++)
        for (int bb = a; bb < XD; bb++) {
            double term = mom[j++] * wc[a] * wc[bb];
            q += (a == bb) ? term : 2.0 * term;
        }
    double Ey2 = (q + 2.0 * b * sxw + cnt * b * b) / den;
    double var = Ey2 - ym * ym;
    if (var < 0) var = 0;
    g_ym[c]   = (float)ym;
    g_apre[c] = (float)((double)g_pre[c] / sqrt(var + 1e-5));
}

// ---------------- kernel 5: KP conv + out for active voxels ----------------
__global__ void __launch_bounds__(64) k_activeout(
        const float* __restrict__ pts, const float* __restrict__ kp,
        const float* __restrict__ kpw, const float* __restrict__ w_pre,
        const float* __restrict__ b_pre, const float* __restrict__ be_pre,
        int G, float vs, int sbase, int scale) {
    __shared__ float sw[XD * OC];
    __shared__ float skp[NKP * 3];
    __shared__ float ss[NKP * OC];
    int c = threadIdx.x;
    for (int i = c; i < XD * OC; i += 64) sw[i] = w_pre[i];
    if (c < NKP * 3) skp[c] = kp[c];
    float ym = g_ym[c], al = g_apre[c], be = be_pre[c], bp = b_pre[c];
    int nact = g_nactive[scale];
    for (int i = blockIdx.x; i < nact; i += gridDim.x) {
        __syncthreads();   // sw/skp visible (1st iter); ss reuse safe (later iters)
        int v = g_active[i];
        float sreg[NKP];
        #pragma unroll
        for (int q = 0; q < NKP; q++) sreg[q] = 0.f;
        unsigned kmask = 0;   // identical across threads (pure geometry)
        float cx = g_cent[v * 3 + 0], cy = g_cent[v * 3 + 1], cz = g_cent[v * 3 + 2];
        float n  = (float)g_npts[v];
        float ax = (float)(v % G) + vs * 0.5f;
        float ay = (float)(v / G) + vs * 0.5f;
        for (int k = 0; k < KCAP; k++) {
            int idx = g_slots[sbase + v * KCAP + k];
            if (idx == SENT) continue;
            float a  = __ldg(&pts[idx * 5 + 0]);
            float b  = __ldg(&pts[idx * 5 + 1]);
            float zc = __ldg(&pts[idx * 5 + 2]);
            float f0 = __ldg(&pts[idx * 5 + 3]);
            float f1 = __ldg(&pts[idx * 5 + 4]);
            float x[XD];
            x[0] = f0; x[1] = f1;
            x[2] = a - ax; x[3] = b - ay; x[4] = zc - 4.0f;
            x[5] = a - cx; x[6] = b - cy; x[7] = zc - cz;
            x[8] = cx; x[9] = cy; x[10] = cz; x[11] = n;
            float y = bp;
            #pragma unroll
            for (int q2 = 0; q2 < XD; q2++) y += x[q2] * sw[q2 * OC + c];
            y = (y - ym) * al + be;
            y = fmaxf(y, 0.f);
            float dx = x[2], dy = x[3], dz = x[4];
            #pragma unroll
            for (int q = 0; q < NKP; q++) {
                float ex = dx - skp[q * 3 + 0];
                float ey = dy - skp[q * 3 + 1];
                float ez = dz - skp[q * 3 + 2];
                float d2 = ex * ex + ey * ey + ez * ez;
                float h = 1.0f - sqrtf(d2 + 1e-12f);
                if (h > 0.f) { sreg[q] += h * y; kmask |= (1u << q); }
            }
        }
        #pragma unroll
        for (int q = 0; q < NKP; q++) ss[q * OC + c] = sreg[q];
        __syncthreads();
        float acc = 0.f;
        for (int q = 0; q < NKP; q++) {
            if (!((kmask >> q) & 1)) continue;
            #pragma unroll 8
            for (int c2 = 0; c2 < OC; c2++)
                acc += ss[q * OC + c2] * __ldg(&kpw[(q * OC + c2) * OC + c]);
        }
        g_out[(size_t)i * OC + c] = acc;
    }
}

// ---------------- kernel 6: S1 / S2 over active outs ----------------
__global__ void k_poststats(int scale) {
    int t = blockIdx.x * blockDim.x + threadIdx.x;
    int n = g_nactive[scale];
    if (t < OC * OC) {
        int c1 = t >> 6, c2 = t & 63;
        double s = 0;
        for (int i = 0; i < n; i++)
            s += (double)g_out[(size_t)i * OC + c1] * (double)g_out[(size_t)i * OC + c2];
        g_S2[t] = s;
    } else if (t < OC * OC + OC) {
        int cc = t - OC * OC;
        double s = 0;
        for (int i = 0; i < n; i++) s += (double)g_out[(size_t)i * OC + cc];
        g_S1[cc] = s;
    }
}

// ---------------- kernel 7: finalize post-BN params + fill constants ----------------
__global__ void k_postfin(const float* __restrict__ w_post, const float* __restrict__ b_post,
                          const float* __restrict__ g_post, const float* __restrict__ be_post,
                          int V) {
    int c = threadIdx.x;
    if (c >= OC) return;
    double m1 = 0;
    for (int k = 0; k < OC; k++) m1 += g_S1[k] * (double)w_post[k * OC + c];
    double q = 0;
    for (int a = 0; a < OC; a++) {
        double wa = (double)w_post[a * OC + c];
        double acc = 0;
        for (int b = 0; b < OC; b++) acc += g_S2[a * OC + b] * (double)w_post[b * OC + c];
        q += wa * acc;
    }
    double bb = (double)b_post[c];
    double Vd = (double)V;
    double mean = m1 / Vd + bb;
    double Ez2 = (q + 2.0 * bb * m1) / Vd + bb * bb;
    double var = Ez2 - mean * mean;
    if (var < 0) var = 0;
    double alpha = (double)g_post[c] / sqrt(var + 1e-5);
    g_pmean[c]  = (float)mean;
    g_palpha[c] = (float)alpha;
    float fill = (float)((bb - mean) * alpha + (double)be_post[c]);
    g_fill[c] = fmaxf(fill, 0.f);
}

// ---------------- kernel 8: fill output plane (vectorized, per-channel constant) ----------------
__global__ void k_fill4(float4* __restrict__ out4, int V) {
    int e = blockIdx.x * blockDim.x + threadIdx.x;        // in float4 units
    int tot = OC * (V >> 2);
    if (e >= tot) return;
    float f = g_fill[e / (V >> 2)];
    out4[e] = make_float4(f, f, f, f);
}

// ---------------- kernel 9: scatter active-voxel outputs ----------------
__global__ void __launch_bounds__(64) k_scatter(float* __restrict__ out,
        const float* __restrict__ w_post, const float* __restrict__ b_post,
        const float* __restrict__ be_post, int V, int scale) {
    int c = threadIdx.x;
    int n = g_nactive[scale];
    float pm = g_pmean[c], pa = g_palpha[c], be = be_post[c];
    for (int i = blockIdx.x; i < n; i += gridDim.x) {
        int v = g_active[i];
        float z = b_post[c];
        #pragma unroll 8
        for (int k = 0; k < OC; k++)
            z += g_out[(size_t)i * OC + k] * __ldg(&w_post[k * OC + c]);
        float zn = fmaxf((z - pm) * pa + be, 0.f);
        out[(size_t)c * V + v] = zn;
    }
}

// ---------------- launcher ----------------
extern "C" void kernel_launch(void* const* d_in, const int* in_sizes, int n_in,
                              void* d_out, int out_size) {
    const float* pts     = (const float*)d_in[0];
    const float* kp      = (const float*)d_in[1];
    const float* w_pre   = (const float*)d_in[2];
    const float* b_pre   = (const float*)d_in[3];
    const float* g_pre   = (const float*)d_in[4];
    const float* be_pre  = (const float*)d_in[5];
    const float* kpw     = (const float*)d_in[6];
    const float* w_post  = (const float*)d_in[7];
    const float* b_post  = (const float*)d_in[8];
    const float* g_post  = (const float*)d_in[9];
    const float* be_post = (const float*)d_in[10];
    float* out = (float*)d_out;
    int N = in_sizes[0] / 5;

    k_init<<<(NSLOT_TOT + 255) / 256, 256>>>();
    if (N > 0) k_insert<<<(N + 255) / 256, 256>>>(pts, N);

    int G = 256;
    float vs = 0.4f;
    int sbase = 0;
    size_t base = 0;
    for (int s = 0; s < 4; s++) {
        int V = G * G;
        k_voxstats <<<V / 256, 256>>>(pts, kp, G, vs, sbase, s);
        k_prebn    <<<1, 64>>>(w_pre, b_pre, g_pre, s);
        k_activeout<<<256, 64>>>(pts, kp, kpw, w_pre, b_pre, be_pre, G, vs, sbase, s);
        k_poststats<<<17, 256>>>(s);
        k_postfin  <<<1, 64>>>(w_post, b_post, g_post, be_post, V);
        k_fill4    <<<(OC * (V >> 2) + 255) / 256, 256>>>((float4*)(out + base), V);
        k_scatter  <<<256, 64>>>(out + base, w_post, b_post, be_post, V, s);
        base += (size_t)OC * V;
        sbase += V * KCAP;
        G >>= 1;
        vs *= 2.0f;
    }
}

// round 10
// speedup vs baseline: 1.7810x; 1.7810x over previous
#include <cuda_runtime.h>
#include <cstdint>

#define KCAP 8
#define NKP 15
#define OC 64
#define XD 12
#define NMOM 91            // cnt(1) + Sx(12) + Sxx upper-tri(78)
#define SENT 0x7FFFFFFF
#define VMAX 65536
#define NSLOT_TOT ((65536 + 16384 + 4096 + 1024) * KCAP)   // 696320

// ---------------- device scratch (static, no allocs) ----------------
__device__ int    g_slots[NSLOT_TOT];       // per-scale regions, K smallest point idx per voxel
__device__ float  g_cent[VMAX * 3];
__device__ int    g_npts[VMAX];
__device__ int    g_active[VMAX];
__device__ int    g_nactive[4];
__device__ double g_mom[4 * 92];            // per scale: [0]=cnt, [1..12]=Sx, [13..90]=Sxx
__device__ float  g_ym[OC];
__device__ float  g_apre[OC];
__device__ double g_S1[OC];
__device__ double g_S2[OC * OC];
__device__ float  g_out[(size_t)VMAX * OC]; // per-active-voxel KP-conv output
__device__ float  g_pmean[OC], g_palpha[OC], g_fill[OC];

// ---------------- kernel 1: init all scratch once ----------------
__global__ void k_init() {
    int i = blockIdx.x * blockDim.x + threadIdx.x;
    if (i < NSLOT_TOT) g_slots[i] = SENT;
    if (i < 4 * 92) g_mom[i] = 0.0;
    if (i < 4) g_nactive[i] = 0;
}

// ---------------- kernel 2: fused 4-scale insert (first-K by original index) ----------------
__global__ void k_insert(const float* __restrict__ pts, int N) {
    int i = blockIdx.x * blockDim.x + threadIdx.x;
    if (i >= N) return;
    float x = pts[i * 5 + 0], y = pts[i * 5 + 1], z = pts[i * 5 + 2];
    if (!(z >= -5.0f && z < 3.0f)) return;
    float bx = x + 51.2f, by = y + 51.2f;
    int sbase = 0, G = 256;
    float vs = 0.4f;
    #pragma unroll
    for (int s = 0; s < 4; s++) {
        float fx = floorf(bx / vs), fy = floorf(by / vs);
        if (fx >= 0.f && fy >= 0.f && fx < (float)G && fy < (float)G) {
            int ix = (int)fx, iy = (int)fy;
            int* sl = &g_slots[sbase + (iy * G + ix) * KCAP];
            int val = i;
            #pragma unroll
            for (int k = 0; k < KCAP; k++) {
                int cur = sl[k];            // racy pre-check OK: slot values only decrease
                if (cur < val) continue;    // val belongs strictly deeper
                int old = atomicMin(&sl[k], val);
                if (old == SENT) break;     // placed in empty tail slot
                val = max(val, old);        // carry larger index deeper
            }
        }
        sbase += G * G * KCAP;
        G >>= 1;
        vs *= 2.0f;
    }
}

// ---------------- kernel 3: fused per-voxel centroid + active detect + moments ----------------
__global__ void __launch_bounds__(256) k_voxstats(
        const float* __restrict__ pts, const float* __restrict__ kp,
        int G, float vs, int sbase, int scale) {
    __shared__ float skp[NKP * 3];
    __shared__ float sAcc[NMOM];
    int t = threadIdx.x, lane = t & 31;
    if (t < NKP * 3) skp[t] = kp[t];
    if (t < NMOM) sAcc[t] = 0.f;
    __syncthreads();

    int v = blockIdx.x * 256 + t;           // V is always a multiple of 256
    const int* sl = &g_slots[sbase + v * KCAP];
    float ax = (float)(v % G) + vs * 0.5f;  // reference's index-space anchor + vs/2
    float ay = (float)(v / G) + vs * 0.5f;

    // pass 1: count / centroid / active
    int idxs[KCAP];
    int cnt = 0;
    float sx = 0.f, sy = 0.f, sz = 0.f;
    bool act = false;
    #pragma unroll
    for (int k = 0; k < KCAP; k++) {
        int idx = sl[k];
        idxs[k] = idx;
        if (idx == SENT) continue;
        float a = __ldg(&pts[idx * 5 + 0]);
        float b = __ldg(&pts[idx * 5 + 1]);
        float c = __ldg(&pts[idx * 5 + 2]);
        sx += a; sy += b; sz += c; cnt++;
        if (!act) {
            float dx = a - ax, dy = b - ay, dz = c - 4.0f;
            #pragma unroll
            for (int q = 0; q < NKP; q++) {
                float ex = dx - skp[q * 3 + 0];
                float ey = dy - skp[q * 3 + 1];
                float ez = dz - skp[q * 3 + 2];
                if (ex * ex + ey * ey + ez * ez < 1.0f) { act = true; break; }
            }
        }
    }
    g_npts[v] = cnt;
    float nf = (float)max(cnt, 1);
    float cx = sx / nf, cy = sy / nf, cz = sz / nf;
    g_cent[v * 3 + 0] = cx;
    g_cent[v * 3 + 1] = cy;
    g_cent[v * 3 + 2] = cz;
    if (act) { int p = atomicAdd(&g_nactive[scale], 1); g_active[p] = v; }

    // pass 2: per-thread moment accumulation (point rows hot in L1)
    float m1[XD];
    float m2[78];
    #pragma unroll
    for (int i2 = 0; i2 < XD; i2++) m1[i2] = 0.f;
    #pragma unroll
    for (int i2 = 0; i2 < 78; i2++) m2[i2] = 0.f;
    float n = (float)cnt;
    #pragma unroll
    for (int k = 0; k < KCAP; k++) {
        int idx = idxs[k];
        if (idx == SENT) continue;
        float a  = __ldg(&pts[idx * 5 + 0]);
        float b  = __ldg(&pts[idx * 5 + 1]);
        float c  = __ldg(&pts[idx * 5 + 2]);
        float f0 = __ldg(&pts[idx * 5 + 3]);
        float f1 = __ldg(&pts[idx * 5 + 4]);
        float x[XD];
        x[0] = f0; x[1] = f1;
        x[2] = a - ax; x[3] = b - ay; x[4] = c - 4.0f;
        x[5] = a - cx; x[6] = b - cy; x[7] = c - cz;
        x[8] = cx; x[9] = cy; x[10] = cz; x[11] = n;
        #pragma unroll
        for (int i2 = 0; i2 < XD; i2++) m1[i2] += x[i2];
        int j = 0;
        #pragma unroll
        for (int a2 = 0; a2 < XD; a2++)
            #pragma unroll
            for (int b2 = a2; b2 < XD; b2++) { m2[j] += x[a2] * x[b2]; j++; }
    }

    // warp butterfly reductions, lane0 -> shared atomics, then block -> global (double)
    {
        float val = (float)cnt;
        #pragma unroll
        for (int o = 16; o; o >>= 1) val += __shfl_xor_sync(0xffffffffu, val, o);
        if (lane == 0) atomicAdd(&sAcc[0], val);
    }
    #pragma unroll
    for (int i2 = 0; i2 < XD; i2++) {
        float val = m1[i2];
        #pragma unroll
        for (int o = 16; o; o >>= 1) val += __shfl_xor_sync(0xffffffffu, val, o);
        if (lane == 0) atomicAdd(&sAcc[1 + i2], val);
    }
    #pragma unroll
    for (int i2 = 0; i2 < 78; i2++) {
        float val = m2[i2];
        #pragma unroll
        for (int o = 16; o; o >>= 1) val += __shfl_xor_sync(0xffffffffu, val, o);
        if (lane == 0) atomicAdd(&sAcc[13 + i2], val);
    }
    __syncthreads();
    if (t < NMOM) atomicAdd(&g_mom[scale * 92 + t], (double)sAcc[t]);
}

// ---------------- kernel 4: pre-BN finalize, latency-parallel ----------------
// 1024 threads: 16 threads per channel split the 78 second-moment terms.
__global__ void __launch_bounds__(1024) k_prebn(
        const float* __restrict__ w_pre, const float* __restrict__ b_pre,
        const float* __restrict__ g_pre, int scale) {
    int t = threadIdx.x;
    int c = t >> 4, p = t & 15;
    const double* mom = &g_mom[scale * 92];
    double wc[XD];
    #pragma unroll
    for (int i = 0; i < XD; i++) wc[i] = (double)w_pre[i * OC + c];
    double sxw_p = 0;
    #pragma unroll
    for (int i = p; i < XD; i += 16) sxw_p += mom[1 + i] * wc[i];
    double q_p = 0;
    int j = 0;
    #pragma unroll
    for (int a = 0; a < XD; a++)
        #pragma unroll
        for (int b = a; b < XD; b++) {
            if ((j & 15) == p) {
                double term = mom[13 + j] * wc[a] * wc[b];
                q_p += (a == b) ? term : 2.0 * term;
            }
            j++;
        }
    #pragma unroll
    for (int o = 8; o; o >>= 1) {            // reduce within 16-lane channel group
        sxw_p += __shfl_xor_sync(0xffffffffu, sxw_p, o);
        q_p   += __shfl_xor_sync(0xffffffffu, q_p, o);
    }
    if (p == 0) {
        double cnt = mom[0];
        double den = cnt > 1.0 ? cnt : 1.0;
        double b = (double)b_pre[c];
        double ym = (sxw_p + cnt * b) / den;
        double Ey2 = (q_p + 2.0 * b * sxw_p + cnt * b * b) / den;
        double var = Ey2 - ym * ym;
        if (var < 0) var = 0;
        g_ym[c]   = (float)ym;
        g_apre[c] = (float)((double)g_pre[c] / sqrt(var + 1e-5));
    }
}

// ---------------- kernel 5: KP conv + out for active voxels ----------------
__global__ void __launch_bounds__(64) k_activeout(
        const float* __restrict__ pts, const float* __restrict__ kp,
        const float* __restrict__ kpw, const float* __restrict__ w_pre,
        const float* __restrict__ b_pre, const float* __restrict__ be_pre,
        int G, float vs, int sbase, int scale) {
    __shared__ float sw[XD * OC];
    __shared__ float skp[NKP * 3];
    __shared__ float ss[NKP * OC];
    int c = threadIdx.x;
    for (int i = c; i < XD * OC; i += 64) sw[i] = w_pre[i];
    if (c < NKP * 3) skp[c] = kp[c];
    float ym = g_ym[c], al = g_apre[c], be = be_pre[c], bp = b_pre[c];
    int nact = g_nactive[scale];
    for (int i = blockIdx.x; i < nact; i += gridDim.x) {
        __syncthreads();   // sw/skp visible (1st iter); ss reuse safe (later iters)
        int v = g_active[i];
        float sreg[NKP];
        #pragma unroll
        for (int q = 0; q < NKP; q++) sreg[q] = 0.f;
        unsigned kmask = 0;   // identical across threads (pure geometry)
        float cx = g_cent[v * 3 + 0], cy = g_cent[v * 3 + 1], cz = g_cent[v * 3 + 2];
        float n  = (float)g_npts[v];
        float ax = (float)(v % G) + vs * 0.5f;
        float ay = (float)(v / G) + vs * 0.5f;
        for (int k = 0; k < KCAP; k++) {
            int idx = g_slots[sbase + v * KCAP + k];
            if (idx == SENT) continue;
            float a  = __ldg(&pts[idx * 5 + 0]);
            float b  = __ldg(&pts[idx * 5 + 1]);
            float zc = __ldg(&pts[idx * 5 + 2]);
            float f0 = __ldg(&pts[idx * 5 + 3]);
            float f1 = __ldg(&pts[idx * 5 + 4]);
            float x[XD];
            x[0] = f0; x[1] = f1;
            x[2] = a - ax; x[3] = b - ay; x[4] = zc - 4.0f;
            x[5] = a - cx; x[6] = b - cy; x[7] = zc - cz;
            x[8] = cx; x[9] = cy; x[10] = cz; x[11] = n;
            float y = bp;
            #pragma unroll
            for (int q2 = 0; q2 < XD; q2++) y += x[q2] * sw[q2 * OC + c];
            y = (y - ym) * al + be;
            y = fmaxf(y, 0.f);
            float dx = x[2], dy = x[3], dz = x[4];
            #pragma unroll
            for (int q = 0; q < NKP; q++) {
                float ex = dx - skp[q * 3 + 0];
                float ey = dy - skp[q * 3 + 1];
                float ez = dz - skp[q * 3 + 2];
                float d2 = ex * ex + ey * ey + ez * ez;
                float h = 1.0f - sqrtf(d2 + 1e-12f);
                if (h > 0.f) { sreg[q] += h * y; kmask |= (1u << q); }
            }
        }
        #pragma unroll
        for (int q = 0; q < NKP; q++) ss[q * OC + c] = sreg[q];
        __syncthreads();
        float acc = 0.f;
        for (int q = 0; q < NKP; q++) {
            if (!((kmask >> q) & 1)) continue;
            #pragma unroll 8
            for (int c2 = 0; c2 < OC; c2++)
                acc += ss[q * OC + c2] * __ldg(&kpw[(q * OC + c2) * OC + c]);
        }
        g_out[(size_t)i * OC + c] = acc;
    }
}

// ---------------- kernel 6: S1 / S2 over active outs ----------------
__global__ void k_poststats(int scale) {
    int t = blockIdx.x * blockDim.x + threadIdx.x;
    int n = g_nactive[scale];
    if (t < OC * OC) {
        int c1 = t >> 6, c2 = t & 63;
        double s = 0;
        for (int i = 0; i < n; i++)
            s += (double)g_out[(size_t)i * OC + c1] * (double)g_out[(size_t)i * OC + c2];
        g_S2[t] = s;
    } else if (t < OC * OC + OC) {
        int cc = t - OC * OC;
        double s = 0;
        for (int i = 0; i < n; i++) s += (double)g_out[(size_t)i * OC + cc];
        g_S1[cc] = s;
    }
}

// ---------------- kernel 7: post-BN finalize, latency-parallel ----------------
// one block per output channel c; 256 threads split the 4096-term w^T S2 w sum.
__global__ void __launch_bounds__(256) k_postfin(
        const float* __restrict__ w_post, const float* __restrict__ b_post,
        const float* __restrict__ g_post, const float* __restrict__ be_post,
        int V) {
    __shared__ double sq[8], sm1[8];
    int c = blockIdx.x, t = threadIdx.x, lane = t & 31, w = t >> 5;
    double q_p = 0;
    #pragma unroll
    for (int r = 0; r < 16; r++) {
        int m = t + r * 256;                 // (a, b) pair index
        int a = m >> 6, b = m & 63;
        q_p += (double)w_post[a * OC + c] * g_S2[m] * (double)w_post[b * OC + c];
    }
    double m1_p = (t < OC) ? g_S1[t] * (double)w_post[t * OC + c] : 0.0;
    #pragma unroll
    for (int o = 16; o; o >>= 1) {
        q_p  += __shfl_xor_sync(0xffffffffu, q_p, o);
        m1_p += __shfl_xor_sync(0xffffffffu, m1_p, o);
    }
    if (lane == 0) { sq[w] = q_p; sm1[w] = m1_p; }
    __syncthreads();
    if (t == 0) {
        double q = 0, m1 = 0;
        #pragma unroll
        for (int i = 0; i < 8; i++) { q += sq[i]; m1 += sm1[i]; }
        double bb = (double)b_post[c];
        double Vd = (double)V;
        double mean = m1 / Vd + bb;
        double Ez2 = (q + 2.0 * bb * m1) / Vd + bb * bb;
        double var = Ez2 - mean * mean;
        if (var < 0) var = 0;
        double alpha = (double)g_post[c] / sqrt(var + 1e-5);
        g_pmean[c]  = (float)mean;
        g_palpha[c] = (float)alpha;
        float fill = (float)((bb - mean) * alpha + (double)be_post[c]);
        g_fill[c] = fmaxf(fill, 0.f);
    }
}

// ---------------- kernel 8: fill output plane (vectorized, per-channel constant) ----------------
__global__ void k_fill4(float4* __restrict__ out4, int V) {
    int e = blockIdx.x * blockDim.x + threadIdx.x;        // in float4 units
    int tot = OC * (V >> 2);
    if (e >= tot) return;
    float f = g_fill[e / (V >> 2)];
    out4[e] = make_float4(f, f, f, f);
}

// ---------------- kernel 9: scatter active-voxel outputs ----------------
__global__ void __launch_bounds__(64) k_scatter(float* __restrict__ out,
        const float* __restrict__ w_post, const float* __restrict__ b_post,
        const float* __restrict__ be_post, int V, int scale) {
    int c = threadIdx.x;
    int n = g_nactive[scale];
    float pm = g_pmean[c], pa = g_palpha[c], be = be_post[c];
    for (int i = blockIdx.x; i < n; i += gridDim.x) {
        int v = g_active[i];
        float z = b_post[c];
        #pragma unroll 8
        for (int k = 0; k < OC; k++)
            z += g_out[(size_t)i * OC + k] * __ldg(&w_post[k * OC + c]);
        float zn = fmaxf((z - pm) * pa + be, 0.f);
        out[(size_t)c * V + v] = zn;
    }
}

// ---------------- launcher ----------------
extern "C" void kernel_launch(void* const* d_in, const int* in_sizes, int n_in,
                              void* d_out, int out_size) {
    const float* pts     = (const float*)d_in[0];
    const float* kp      = (const float*)d_in[1];
    const float* w_pre   = (const float*)d_in[2];
    const float* b_pre   = (const float*)d_in[3];
    const float* g_pre   = (const float*)d_in[4];
    const float* be_pre  = (const float*)d_in[5];
    const float* kpw     = (const float*)d_in[6];
    const float* w_post  = (const float*)d_in[7];
    const float* b_post  = (const float*)d_in[8];
    const float* g_post  = (const float*)d_in[9];
    const float* be_post = (const float*)d_in[10];
    float* out = (float*)d_out;
    int N = in_sizes[0] / 5;

    k_init<<<(NSLOT_TOT + 255) / 256, 256>>>();
    if (N > 0) k_insert<<<(N + 255) / 256, 256>>>(pts, N);

    int G = 256;
    float vs = 0.4f;
    int sbase = 0;
    size_t base = 0;
    for (int s = 0; s < 4; s++) {
        int V = G * G;
        k_voxstats <<<V / 256, 256>>>(pts, kp, G, vs, sbase, s);
        k_prebn    <<<1, 1024>>>(w_pre, b_pre, g_pre, s);
        k_activeout<<<256, 64>>>(pts, kp, kpw, w_pre, b_pre, be_pre, G, vs, sbase, s);
        k_poststats<<<17, 256>>>(s);
        k_postfin  <<<64, 256>>>(w_post, b_post, g_post, be_post, V);
        k_fill4    <<<(OC * (V >> 2) + 255) / 256, 256>>>((float4*)(out + base), V);
        k_scatter  <<<256, 64>>>(out + base, w_post, b_post, be_post, V, s);
        base += (size_t)OC * V;
        sbase += V * KCAP;
        G >>= 1;
        vs *= 2.0f;
    }
}

// round 11
// speedup vs baseline: 6.0015x; 3.3697x over previous
#include <cuda_runtime.h>
#include <cstdint>

#define KCAP 8
#define NKP 15
#define OC 64
#define XD 12
#define NMOM 91            // cnt(1) + Sx(12) + Sxx upper-tri(78)
#define SENT 0x7FFFFFFF
#define NVOX_TOT 87040     // 65536 + 16384 + 4096 + 1024
#define NSLOT_TOT (NVOX_TOT * KCAP)

// per-scale voxel offsets (cumulative V); also active-list and output-plane offsets
__device__ __constant__ int c_VOFF[5] = {0, 65536, 81920, 86016, 87040};
// upper-triangle (a,b) pairs for XD=12 second moments
__device__ __constant__ signed char c_triA[78] = {
    0,0,0,0,0,0,0,0,0,0,0,0, 1,1,1,1,1,1,1,1,1,1,1, 2,2,2,2,2,2,2,2,2,2,
    3,3,3,3,3,3,3,3,3, 4,4,4,4,4,4,4,4, 5,5,5,5,5,5,5, 6,6,6,6,6,6,
    7,7,7,7,7, 8,8,8,8, 9,9,9, 10,10, 11};
__device__ __constant__ signed char c_triB[78] = {
    0,1,2,3,4,5,6,7,8,9,10,11, 1,2,3,4,5,6,7,8,9,10,11, 2,3,4,5,6,7,8,9,10,11,
    3,4,5,6,7,8,9,10,11, 4,5,6,7,8,9,10,11, 5,6,7,8,9,10,11, 6,7,8,9,10,11,
    7,8,9,10,11, 8,9,10,11, 9,10,11, 10,11, 11};

// ---------------- device scratch (static, no allocs) ----------------
__device__ int    g_slots[NSLOT_TOT];
__device__ float  g_cent[NVOX_TOT * 3];
__device__ int    g_npts[NVOX_TOT];
__device__ int    g_active[NVOX_TOT];        // per-scale regions at c_VOFF
__device__ int    g_nactive[4];
__device__ double g_mom[4 * 92];
__device__ float  g_ym[4 * OC];
__device__ float  g_apre[4 * OC];
__device__ double g_S1[4 * OC];
__device__ double g_S2[4 * OC * OC];
__device__ float  g_out[(size_t)NVOX_TOT * OC];
__device__ float  g_pmean[4 * OC], g_palpha[4 * OC], g_fill[4 * OC];

// ---------------- kernel 1: init ----------------
__global__ void k_init() {
    int i = blockIdx.x * blockDim.x + threadIdx.x;
    if (i < NSLOT_TOT) g_slots[i] = SENT;
    if (i < 4 * 92) g_mom[i] = 0.0;
    if (i < 4) g_nactive[i] = 0;
}

// ---------------- kernel 2: fused 4-scale insert (first-K by original index) ----------------
__global__ void k_insert(const float* __restrict__ pts, int N) {
    int i = blockIdx.x * blockDim.x + threadIdx.x;
    if (i >= N) return;
    float x = pts[i * 5 + 0], y = pts[i * 5 + 1], z = pts[i * 5 + 2];
    if (!(z >= -5.0f && z < 3.0f)) return;
    float bx = x + 51.2f, by = y + 51.2f;
    int G = 256;
    float vs = 0.4f;
    #pragma unroll
    for (int s = 0; s < 4; s++) {
        float fx = floorf(bx / vs), fy = floorf(by / vs);
        if (fx >= 0.f && fy >= 0.f && fx < (float)G && fy < (float)G) {
            int ix = (int)fx, iy = (int)fy;
            int* sl = &g_slots[(c_VOFF[s] + iy * G + ix) * KCAP];
            int val = i;
            #pragma unroll
            for (int k = 0; k < KCAP; k++) {
                int cur = sl[k];            // racy pre-check OK: slot values only decrease
                if (cur < val) continue;
                int old = atomicMin(&sl[k], val);
                if (old == SENT) break;
                val = max(val, old);
            }
        }
        G >>= 1;
        vs *= 2.0f;
    }
}

// ---------------- kernel 3: all-scale centroid + active detect + moments ----------------
__global__ void __launch_bounds__(256) k_voxstats(
        const float* __restrict__ pts, const float* __restrict__ kp) {
    __shared__ float skp[NKP * 3];
    __shared__ float sAcc[NMOM];
    int t = threadIdx.x, lane = t & 31;
    if (t < NKP * 3) skp[t] = kp[t];
    if (t < NMOM) sAcc[t] = 0.f;
    __syncthreads();

    int gv = blockIdx.x * 256 + t;              // global voxel index (all scales)
    int s = (gv < 65536) ? 0 : (gv < 81920) ? 1 : (gv < 86016) ? 2 : 3;
    int v = gv - c_VOFF[s];
    int G = 256 >> s;
    float vs = 0.4f * (float)(1 << s);
    const int* sl = &g_slots[gv * KCAP];
    float ax = (float)(v & (G - 1)) + vs * 0.5f;
    float ay = (float)(v >> (8 - s)) + vs * 0.5f;

    int idxs[KCAP];
    int cnt = 0;
    float sx = 0.f, sy = 0.f, sz = 0.f;
    bool act = false;
    #pragma unroll
    for (int k = 0; k < KCAP; k++) {
        int idx = sl[k];
        idxs[k] = idx;
        if (idx == SENT) continue;
        float a = __ldg(&pts[idx * 5 + 0]);
        float b = __ldg(&pts[idx * 5 + 1]);
        float c = __ldg(&pts[idx * 5 + 2]);
        sx += a; sy += b; sz += c; cnt++;
        if (!act) {
            float dx = a - ax, dy = b - ay, dz = c - 4.0f;
            #pragma unroll
            for (int q = 0; q < NKP; q++) {
                float ex = dx - skp[q * 3 + 0];
                float ey = dy - skp[q * 3 + 1];
                float ez = dz - skp[q * 3 + 2];
                if (ex * ex + ey * ey + ez * ez < 1.0f) { act = true; break; }
            }
        }
    }
    g_npts[gv] = cnt;
    float nf = (float)max(cnt, 1);
    float cx = sx / nf, cy = sy / nf, cz = sz / nf;
    g_cent[gv * 3 + 0] = cx;
    g_cent[gv * 3 + 1] = cy;
    g_cent[gv * 3 + 2] = cz;
    if (act) { int p = atomicAdd(&g_nactive[s], 1); g_active[c_VOFF[s] + p] = v; }

    float m1[XD];
    float m2[78];
    #pragma unroll
    for (int i2 = 0; i2 < XD; i2++) m1[i2] = 0.f;
    #pragma unroll
    for (int i2 = 0; i2 < 78; i2++) m2[i2] = 0.f;
    float n = (float)cnt;
    #pragma unroll
    for (int k = 0; k < KCAP; k++) {
        int idx = idxs[k];
        if (idx == SENT) continue;
        float a  = __ldg(&pts[idx * 5 + 0]);
        float b  = __ldg(&pts[idx * 5 + 1]);
        float c  = __ldg(&pts[idx * 5 + 2]);
        float f0 = __ldg(&pts[idx * 5 + 3]);
        float f1 = __ldg(&pts[idx * 5 + 4]);
        float x[XD];
        x[0] = f0; x[1] = f1;
        x[2] = a - ax; x[3] = b - ay; x[4] = c - 4.0f;
        x[5] = a - cx; x[6] = b - cy; x[7] = c - cz;
        x[8] = cx; x[9] = cy; x[10] = cz; x[11] = n;
        #pragma unroll
        for (int i2 = 0; i2 < XD; i2++) m1[i2] += x[i2];
        int j = 0;
        #pragma unroll
        for (int a2 = 0; a2 < XD; a2++)
            #pragma unroll
            for (int b2 = a2; b2 < XD; b2++) { m2[j] += x[a2] * x[b2]; j++; }
    }

    {
        float val = (float)cnt;
        #pragma unroll
        for (int o = 16; o; o >>= 1) val += __shfl_xor_sync(0xffffffffu, val, o);
        if (lane == 0) atomicAdd(&sAcc[0], val);
    }
    #pragma unroll
    for (int i2 = 0; i2 < XD; i2++) {
        float val = m1[i2];
        #pragma unroll
        for (int o = 16; o; o >>= 1) val += __shfl_xor_sync(0xffffffffu, val, o);
        if (lane == 0) atomicAdd(&sAcc[1 + i2], val);
    }
    #pragma unroll
    for (int i2 = 0; i2 < 78; i2++) {
        float val = m2[i2];
        #pragma unroll
        for (int o = 16; o; o >>= 1) val += __shfl_xor_sync(0xffffffffu, val, o);
        if (lane == 0) atomicAdd(&sAcc[13 + i2], val);
    }
    __syncthreads();
    if (t < NMOM) atomicAdd(&g_mom[s * 92 + t], (double)sAcc[t]);
}

// ---------------- kernel 4: pre-BN finalize, all scales, smem-staged ----------------
__global__ void __launch_bounds__(1024) k_prebn(
        const float* __restrict__ w_pre, const float* __restrict__ b_pre,
        const float* __restrict__ g_pre) {
    __shared__ double smom[92];
    __shared__ float swp[XD * OC];
    int s = blockIdx.x;
    int t = threadIdx.x;
    if (t < 92) smom[t] = g_mom[s * 92 + t];
    if (t < XD * OC) swp[t] = w_pre[t];
    __syncthreads();
    int c = t >> 4, p = t & 15;
    double sxw_p = (p < XD) ? smom[1 + p] * (double)swp[p * OC + c] : 0.0;
    double q_p = 0;
    int j0 = p * 5;
    #pragma unroll
    for (int jj = 0; jj < 5; jj++) {
        int j = j0 + jj;
        if (j < 78) {
            int a = c_triA[j], b = c_triB[j];
            double term = smom[13 + j] * (double)swp[a * OC + c] * (double)swp[b * OC + c];
            q_p += (a == b) ? term : 2.0 * term;
        }
    }
    #pragma unroll
    for (int o = 8; o; o >>= 1) {
        sxw_p += __shfl_xor_sync(0xffffffffu, sxw_p, o);
        q_p   += __shfl_xor_sync(0xffffffffu, q_p, o);
    }
    if (p == 0) {
        double cnt = smom[0];
        double den = cnt > 1.0 ? cnt : 1.0;
        double b = (double)b_pre[c];
        double ym = (sxw_p + cnt * b) / den;
        double Ey2 = (q_p + 2.0 * b * sxw_p + cnt * b * b) / den;
        double var = Ey2 - ym * ym;
        if (var < 0) var = 0;
        g_ym[s * OC + c]   = (float)ym;
        g_apre[s * OC + c] = (float)((double)g_pre[c] / sqrt(var + 1e-5));
    }
}

// ---------------- kernel 5: KP conv + out for active voxels, all scales ----------------
__global__ void __launch_bounds__(64) k_activeout(
        const float* __restrict__ pts, const float* __restrict__ kp,
        const float* __restrict__ kpw, const float* __restrict__ w_pre,
        const float* __restrict__ b_pre, const float* __restrict__ be_pre) {
    __shared__ float sw[XD * OC];
    __shared__ float skp[NKP * 3];
    __shared__ float ss[NKP * OC];
    int s = blockIdx.y;
    int c = threadIdx.x;
    for (int i = c; i < XD * OC; i += 64) sw[i] = w_pre[i];
    if (c < NKP * 3) skp[c] = kp[c];
    int G = 256 >> s;
    float vs = 0.4f * (float)(1 << s);
    int voff = c_VOFF[s];
    float ym = g_ym[s * OC + c], al = g_apre[s * OC + c];
    float be = be_pre[c], bp = b_pre[c];
    int nact = g_nactive[s];
    for (int i = blockIdx.x; i < nact; i += gridDim.x) {
        __syncthreads();
        int v = g_active[voff + i];
        int gv = voff + v;
        float sreg[NKP];
        #pragma unroll
        for (int q = 0; q < NKP; q++) sreg[q] = 0.f;
        unsigned kmask = 0;
        float cx = g_cent[gv * 3 + 0], cy = g_cent[gv * 3 + 1], cz = g_cent[gv * 3 + 2];
        float n  = (float)g_npts[gv];
        float ax = (float)(v & (G - 1)) + vs * 0.5f;
        float ay = (float)(v >> (8 - s)) + vs * 0.5f;
        for (int k = 0; k < KCAP; k++) {
            int idx = g_slots[gv * KCAP + k];
            if (idx == SENT) continue;
            float a  = __ldg(&pts[idx * 5 + 0]);
            float b  = __ldg(&pts[idx * 5 + 1]);
            float zc = __ldg(&pts[idx * 5 + 2]);
            float f0 = __ldg(&pts[idx * 5 + 3]);
            float f1 = __ldg(&pts[idx * 5 + 4]);
            float x[XD];
            x[0] = f0; x[1] = f1;
            x[2] = a - ax; x[3] = b - ay; x[4] = zc - 4.0f;
            x[5] = a - cx; x[6] = b - cy; x[7] = zc - cz;
            x[8] = cx; x[9] = cy; x[10] = cz; x[11] = n;
            float y = bp;
            #pragma unroll
            for (int q2 = 0; q2 < XD; q2++) y += x[q2] * sw[q2 * OC + c];
            y = (y - ym) * al + be;
            y = fmaxf(y, 0.f);
            float dx = x[2], dy = x[3], dz = x[4];
            #pragma unroll
            for (int q = 0; q < NKP; q++) {
                float ex = dx - skp[q * 3 + 0];
                float ey = dy - skp[q * 3 + 1];
                float ez = dz - skp[q * 3 + 2];
                float d2 = ex * ex + ey * ey + ez * ez;
                float h = 1.0f - sqrtf(d2 + 1e-12f);
                if (h > 0.f) { sreg[q] += h * y; kmask |= (1u << q); }
            }
        }
        #pragma unroll
        for (int q = 0; q < NKP; q++) ss[q * OC + c] = sreg[q];
        __syncthreads();
        float acc = 0.f;
        for (int q = 0; q < NKP; q++) {
            if (!((kmask >> q) & 1)) continue;
            #pragma unroll 8
            for (int c2 = 0; c2 < OC; c2++)
                acc += ss[q * OC + c2] * __ldg(&kpw[(q * OC + c2) * OC + c]);
        }
        g_out[(size_t)(voff + i) * OC + c] = acc;
    }
}

// ---------------- kernel 6: S1 / S2 over active outs, all scales, ILP-4 ----------------
__global__ void k_poststats() {
    int s = blockIdx.y;
    int t = blockIdx.x * blockDim.x + threadIdx.x;
    int n = g_nactive[s];
    size_t obase = (size_t)c_VOFF[s] * OC;
    if (t < OC * OC) {
        int c1 = t >> 6, c2 = t & 63;
        double s0 = 0, s1 = 0, s2 = 0, s3 = 0;
        int i = 0;
        for (; i + 4 <= n; i += 4) {
            s0 += (double)g_out[obase + (size_t)(i + 0) * OC + c1] * (double)g_out[obase + (size_t)(i + 0) * OC + c2];
            s1 += (double)g_out[obase + (size_t)(i + 1) * OC + c1] * (double)g_out[obase + (size_t)(i + 1) * OC + c2];
            s2 += (double)g_out[obase + (size_t)(i + 2) * OC + c1] * (double)g_out[obase + (size_t)(i + 2) * OC + c2];
            s3 += (double)g_out[obase + (size_t)(i + 3) * OC + c1] * (double)g_out[obase + (size_t)(i + 3) * OC + c2];
        }
        for (; i < n; i++)
            s0 += (double)g_out[obase + (size_t)i * OC + c1] * (double)g_out[obase + (size_t)i * OC + c2];
        g_S2[s * OC * OC + t] = (s0 + s1) + (s2 + s3);
    } else if (t < OC * OC + OC) {
        int cc = t - OC * OC;
        double s0 = 0;
        for (int i = 0; i < n; i++) s0 += (double)g_out[obase + (size_t)i * OC + cc];
        g_S1[s * OC + cc] = s0;
    }
}

// ---------------- kernel 7: post-BN finalize, all scales ----------------
__global__ void __launch_bounds__(256) k_postfin(
        const float* __restrict__ w_post, const float* __restrict__ b_post,
        const float* __restrict__ g_post, const float* __restrict__ be_post) {
    __shared__ double sq[8], sm1[8];
    int s = blockIdx.y;
    int c = blockIdx.x, t = threadIdx.x, lane = t & 31, w = t >> 5;
    const double* S2 = &g_S2[s * OC * OC];
    double q_p = 0;
    #pragma unroll
    for (int r = 0; r < 16; r++) {
        int m = t + r * 256;
        int a = m >> 6, b = m & 63;
        q_p += (double)w_post[a * OC + c] * S2[m] * (double)w_post[b * OC + c];
    }
    double m1_p = (t < OC) ? g_S1[s * OC + t] * (double)w_post[t * OC + c] : 0.0;
    #pragma unroll
    for (int o = 16; o; o >>= 1) {
        q_p  += __shfl_xor_sync(0xffffffffu, q_p, o);
        m1_p += __shfl_xor_sync(0xffffffffu, m1_p, o);
    }
    if (lane == 0) { sq[w] = q_p; sm1[w] = m1_p; }
    __syncthreads();
    if (t == 0) {
        double q = 0, m1 = 0;
        #pragma unroll
        for (int i = 0; i < 8; i++) { q += sq[i]; m1 += sm1[i]; }
        int V = (256 >> s) * (256 >> s);
        double bb = (double)b_post[c];
        double Vd = (double)V;
        double mean = m1 / Vd + bb;
        double Ez2 = (q + 2.0 * bb * m1) / Vd + bb * bb;
        double var = Ez2 - mean * mean;
        if (var < 0) var = 0;
        double alpha = (double)g_post[c] / sqrt(var + 1e-5);
        g_pmean[s * OC + c]  = (float)mean;
        g_palpha[s * OC + c] = (float)alpha;
        float fill = (float)((bb - mean) * alpha + (double)be_post[c]);
        g_fill[s * OC + c] = fmaxf(fill, 0.f);
    }
}

// ---------------- kernel 8: fill whole output (all scales), vectorized ----------------
__global__ void k_fill4(float4* __restrict__ out4) {
    int e = blockIdx.x * blockDim.x + threadIdx.x;     // float4 units, total 1,392,640
    if (e >= 1392640) return;
    int s, off, sh;
    if (e < 1048576)       { s = 0; off = 0;       sh = 14; }
    else if (e < 1310720)  { s = 1; off = 1048576; sh = 12; }
    else if (e < 1376256)  { s = 2; off = 1310720; sh = 10; }
    else                   { s = 3; off = 1376256; sh = 8;  }
    float f = g_fill[s * OC + ((e - off) >> sh)];
    out4[e] = make_float4(f, f, f, f);
}

// ---------------- kernel 9: scatter active-voxel outputs, all scales ----------------
__global__ void __launch_bounds__(64) k_scatter(float* __restrict__ out,
        const float* __restrict__ w_post, const float* __restrict__ b_post,
        const float* __restrict__ be_post) {
    int s = blockIdx.y;
    int c = threadIdx.x;
    int n = g_nactive[s];
    int V = (256 >> s) * (256 >> s);
    size_t outbase = (size_t)OC * c_VOFF[s];   // output-plane offset == OC * cumulative V
    size_t obase   = (size_t)c_VOFF[s] * OC;
    float pm = g_pmean[s * OC + c], pa = g_palpha[s * OC + c], be = be_post[c];
    for (int i = blockIdx.x; i < n; i += gridDim.x) {
        int v = g_active[c_VOFF[s] + i];
        float z = b_post[c];
        #pragma unroll 8
        for (int k = 0; k < OC; k++)
            z += g_out[obase + (size_t)i * OC + k] * __ldg(&w_post[k * OC + c]);
        float zn = fmaxf((z - pm) * pa + be, 0.f);
        out[outbase + (size_t)c * V + v] = zn;
    }
}

// ---------------- launcher ----------------
extern "C" void kernel_launch(void* const* d_in, const int* in_sizes, int n_in,
                              void* d_out, int out_size) {
    const float* pts     = (const float*)d_in[0];
    const float* kp      = (const float*)d_in[1];
    const float* w_pre   = (const float*)d_in[2];
    const float* b_pre   = (const float*)d_in[3];
    const float* g_pre   = (const float*)d_in[4];
    const float* be_pre  = (const float*)d_in[5];
    const float* kpw     = (const float*)d_in[6];
    const float* w_post  = (const float*)d_in[7];
    const float* b_post  = (const float*)d_in[8];
    const float* g_post  = (const float*)d_in[9];
    const float* be_post = (const float*)d_in[10];
    float* out = (float*)d_out;
    int N = in_sizes[0] / 5;

    k_init     <<<(NSLOT_TOT + 255) / 256, 256>>>();
    if (N > 0) k_insert<<<(N + 255) / 256, 256>>>(pts, N);
    k_voxstats <<<NVOX_TOT / 256, 256>>>(pts, kp);
    k_prebn    <<<4, 1024>>>(w_pre, b_pre, g_pre);
    k_activeout<<<dim3(64, 4), 64>>>(pts, kp, kpw, w_pre, b_pre, be_pre);
    k_poststats<<<dim3(17, 4), 256>>>();
    k_postfin  <<<dim3(64, 4), 256>>>(w_post, b_post, g_post, be_post);
    k_fill4    <<<(1392640 + 255) / 256, 256>>>((float4*)out);
    k_scatter  <<<dim3(64, 4), 64>>>(out, w_post, b_post, be_post);
}

// round 12
// speedup vs baseline: 6.4507x; 1.0748x over previous
#include <cuda_runtime.h>
#include <cstdint>

#define KCAP 8
#define NKP 15
#define OC 64
#define XD 12
#define NMOM 91            // cnt(1) + Sx(12) + Sxx upper-tri(78)
#define SENT 0x7FFFFFFF
#define NVOX_TOT 87040     // 65536 + 16384 + 4096 + 1024
#define NSLOT_TOT (NVOX_TOT * KCAP)

// per-scale voxel offsets (cumulative V); also active-list and output-plane offsets
__device__ __constant__ int c_VOFF[5] = {0, 65536, 81920, 86016, 87040};
// upper-triangle (a,b) pairs for XD=12 second moments — plain __device__ (LDG path),
// NOT __constant__: per-thread divergent LDC serializes 32-way at an 8-cyc floor.
__device__ const signed char d_triA[78] = {
    0,0,0,0,0,0,0,0,0,0,0,0, 1,1,1,1,1,1,1,1,1,1,1, 2,2,2,2,2,2,2,2,2,2,
    3,3,3,3,3,3,3,3,3, 4,4,4,4,4,4,4,4, 5,5,5,5,5,5,5, 6,6,6,6,6,6,
    7,7,7,7,7, 8,8,8,8, 9,9,9, 10,10, 11};
__device__ const signed char d_triB[78] = {
    0,1,2,3,4,5,6,7,8,9,10,11, 1,2,3,4,5,6,7,8,9,10,11, 2,3,4,5,6,7,8,9,10,11,
    3,4,5,6,7,8,9,10,11, 4,5,6,7,8,9,10,11, 5,6,7,8,9,10,11, 6,7,8,9,10,11,
    7,8,9,10,11, 8,9,10,11, 9,10,11, 10,11, 11};

// ---------------- device scratch (static, no allocs) ----------------
__device__ int    g_slots[NSLOT_TOT];
__device__ float  g_cent[NVOX_TOT * 3];
__device__ int    g_npts[NVOX_TOT];
__device__ int    g_active[NVOX_TOT];        // per-scale regions at c_VOFF
__device__ int    g_nactive[4];
__device__ double g_mom[4 * 92];
__device__ float  g_ym[4 * OC];
__device__ float  g_apre[4 * OC];
__device__ double g_S1[4 * OC];
__device__ double g_S2[4 * OC * OC];
__device__ float  g_out[(size_t)NVOX_TOT * OC];
__device__ float  g_pmean[4 * OC], g_palpha[4 * OC], g_fill[4 * OC];

// ---------------- kernel 1: init ----------------
__global__ void k_init() {
    int i = blockIdx.x * blockDim.x + threadIdx.x;
    if (i < NSLOT_TOT) g_slots[i] = SENT;
    if (i < 4 * 92) g_mom[i] = 0.0;
    if (i < 4) g_nactive[i] = 0;
}

// ---------------- kernel 2: fused 4-scale insert (first-K by original index) ----------------
__global__ void k_insert(const float* __restrict__ pts, int N) {
    int i = blockIdx.x * blockDim.x + threadIdx.x;
    if (i >= N) return;
    float x = pts[i * 5 + 0], y = pts[i * 5 + 1], z = pts[i * 5 + 2];
    if (!(z >= -5.0f && z < 3.0f)) return;
    float bx = x + 51.2f, by = y + 51.2f;
    int G = 256;
    float vs = 0.4f;
    #pragma unroll
    for (int s = 0; s < 4; s++) {
        float fx = floorf(bx / vs), fy = floorf(by / vs);
        if (fx >= 0.f && fy >= 0.f && fx < (float)G && fy < (float)G) {
            int ix = (int)fx, iy = (int)fy;
            int* sl = &g_slots[(c_VOFF[s] + iy * G + ix) * KCAP];
            int val = i;
            #pragma unroll
            for (int k = 0; k < KCAP; k++) {
                int cur = sl[k];            // racy pre-check OK: slot values only decrease
                if (cur < val) continue;
                int old = atomicMin(&sl[k], val);
                if (old == SENT) break;
                val = max(val, old);
            }
        }
        G >>= 1;
        vs *= 2.0f;
    }
}

// ---------------- kernel 3: all-scale centroid + active detect + moments ----------------
__global__ void __launch_bounds__(256) k_voxstats(
        const float* __restrict__ pts, const float* __restrict__ kp) {
    __shared__ float skp[NKP * 3];
    __shared__ float sAcc[NMOM];
    int t = threadIdx.x, lane = t & 31;
    if (t < NKP * 3) skp[t] = kp[t];
    if (t < NMOM) sAcc[t] = 0.f;
    __syncthreads();

    int gv = blockIdx.x * 256 + t;              // global voxel index (all scales)
    int s = (gv < 65536) ? 0 : (gv < 81920) ? 1 : (gv < 86016) ? 2 : 3;
    int v = gv - c_VOFF[s];
    int G = 256 >> s;
    float vs = 0.4f * (float)(1 << s);
    const int* sl = &g_slots[gv * KCAP];
    float ax = (float)(v & (G - 1)) + vs * 0.5f;
    float ay = (float)(v >> (8 - s)) + vs * 0.5f;

    int idxs[KCAP];
    int cnt = 0;
    float sx = 0.f, sy = 0.f, sz = 0.f;
    bool act = false;
    #pragma unroll
    for (int k = 0; k < KCAP; k++) {
        int idx = sl[k];
        idxs[k] = idx;
        if (idx == SENT) continue;
        float a = __ldg(&pts[idx * 5 + 0]);
        float b = __ldg(&pts[idx * 5 + 1]);
        float c = __ldg(&pts[idx * 5 + 2]);
        sx += a; sy += b; sz += c; cnt++;
        if (!act) {
            float dx = a - ax, dy = b - ay, dz = c - 4.0f;
            #pragma unroll
            for (int q = 0; q < NKP; q++) {
                float ex = dx - skp[q * 3 + 0];
                float ey = dy - skp[q * 3 + 1];
                float ez = dz - skp[q * 3 + 2];
                if (ex * ex + ey * ey + ez * ez < 1.0f) { act = true; break; }
            }
        }
    }
    g_npts[gv] = cnt;
    float nf = (float)max(cnt, 1);
    float cx = sx / nf, cy = sy / nf, cz = sz / nf;
    g_cent[gv * 3 + 0] = cx;
    g_cent[gv * 3 + 1] = cy;
    g_cent[gv * 3 + 2] = cz;
    if (act) { int p = atomicAdd(&g_nactive[s], 1); g_active[c_VOFF[s] + p] = v; }

    float m1[XD];
    float m2[78];
    #pragma unroll
    for (int i2 = 0; i2 < XD; i2++) m1[i2] = 0.f;
    #pragma unroll
    for (int i2 = 0; i2 < 78; i2++) m2[i2] = 0.f;
    float n = (float)cnt;
    #pragma unroll
    for (int k = 0; k < KCAP; k++) {
        int idx = idxs[k];
        if (idx == SENT) continue;
        float a  = __ldg(&pts[idx * 5 + 0]);
        float b  = __ldg(&pts[idx * 5 + 1]);
        float c  = __ldg(&pts[idx * 5 + 2]);
        float f0 = __ldg(&pts[idx * 5 + 3]);
        float f1 = __ldg(&pts[idx * 5 + 4]);
        float x[XD];
        x[0] = f0; x[1] = f1;
        x[2] = a - ax; x[3] = b - ay; x[4] = c - 4.0f;
        x[5] = a - cx; x[6] = b - cy; x[7] = c - cz;
        x[8] = cx; x[9] = cy; x[10] = cz; x[11] = n;
        #pragma unroll
        for (int i2 = 0; i2 < XD; i2++) m1[i2] += x[i2];
        int j = 0;
        #pragma unroll
        for (int a2 = 0; a2 < XD; a2++)
            #pragma unroll
            for (int b2 = a2; b2 < XD; b2++) { m2[j] += x[a2] * x[b2]; j++; }
    }

    {
        float val = (float)cnt;
        #pragma unroll
        for (int o = 16; o; o >>= 1) val += __shfl_xor_sync(0xffffffffu, val, o);
        if (lane == 0) atomicAdd(&sAcc[0], val);
    }
    #pragma unroll
    for (int i2 = 0; i2 < XD; i2++) {
        float val = m1[i2];
        #pragma unroll
        for (int o = 16; o; o >>= 1) val += __shfl_xor_sync(0xffffffffu, val, o);
        if (lane == 0) atomicAdd(&sAcc[1 + i2], val);
    }
    #pragma unroll
    for (int i2 = 0; i2 < 78; i2++) {
        float val = m2[i2];
        #pragma unroll
        for (int o = 16; o; o >>= 1) val += __shfl_xor_sync(0xffffffffu, val, o);
        if (lane == 0) atomicAdd(&sAcc[13 + i2], val);
    }
    __syncthreads();
    if (t < NMOM) atomicAdd(&g_mom[s * 92 + t], (double)sAcc[t]);
}

// ---------------- kernel 4: pre-BN finalize, smem-staged (double weights, LDG tables) ----------------
__global__ void __launch_bounds__(1024) k_prebn(
        const float* __restrict__ w_pre, const float* __restrict__ b_pre,
        const float* __restrict__ g_pre) {
    __shared__ double smom[92];
    __shared__ double swpd[XD * OC];
    int s = blockIdx.x;
    int t = threadIdx.x;
    if (t < 92) smom[t] = g_mom[s * 92 + t];
    if (t < XD * OC) swpd[t] = (double)w_pre[t];
    __syncthreads();
    int c = t >> 4, p = t & 15;
    double sxw_p = (p < XD) ? smom[1 + p] * swpd[p * OC + c] : 0.0;
    double q_p = 0;
    int j0 = p * 5;
    #pragma unroll
    for (int jj = 0; jj < 5; jj++) {
        int j = j0 + jj;
        if (j < 78) {
            int a = d_triA[j], b = d_triB[j];          // LDG (L1), no constant-port replay
            double term = smom[13 + j] * swpd[a * OC + c] * swpd[b * OC + c];
            q_p += (a == b) ? term : 2.0 * term;
        }
    }
    #pragma unroll
    for (int o = 8; o; o >>= 1) {
        sxw_p += __shfl_xor_sync(0xffffffffu, sxw_p, o);
        q_p   += __shfl_xor_sync(0xffffffffu, q_p, o);
    }
    if (p == 0) {
        double cnt = smom[0];
        double den = cnt > 1.0 ? cnt : 1.0;
        double b = (double)b_pre[c];
        double ym = (sxw_p + cnt * b) / den;
        double Ey2 = (q_p + 2.0 * b * sxw_p + cnt * b * b) / den;
        double var = Ey2 - ym * ym;
        if (var < 0) var = 0;
        g_ym[s * OC + c]   = (float)ym;
        g_apre[s * OC + c] = (float)((double)g_pre[c] / sqrt(var + 1e-5));
    }
}

// ---------------- kernel 5: KP conv + out for active voxels, all scales ----------------
__global__ void __launch_bounds__(64) k_activeout(
        const float* __restrict__ pts, const float* __restrict__ kp,
        const float* __restrict__ kpw, const float* __restrict__ w_pre,
        const float* __restrict__ b_pre, const float* __restrict__ be_pre) {
    __shared__ float sw[XD * OC];
    __shared__ float skp[NKP * 3];
    __shared__ float ss[NKP * OC];
    int s = blockIdx.y;
    int c = threadIdx.x;
    for (int i = c; i < XD * OC; i += 64) sw[i] = w_pre[i];
    if (c < NKP * 3) skp[c] = kp[c];
    int G = 256 >> s;
    float vs = 0.4f * (float)(1 << s);
    int voff = c_VOFF[s];
    float ym = g_ym[s * OC + c], al = g_apre[s * OC + c];
    float be = be_pre[c], bp = b_pre[c];
    int nact = g_nactive[s];
    for (int i = blockIdx.x; i < nact; i += gridDim.x) {
        __syncthreads();
        int v = g_active[voff + i];
        int gv = voff + v;
        float sreg[NKP];
        #pragma unroll
        for (int q = 0; q < NKP; q++) sreg[q] = 0.f;
        unsigned kmask = 0;
        float cx = g_cent[gv * 3 + 0], cy = g_cent[gv * 3 + 1], cz = g_cent[gv * 3 + 2];
        float n  = (float)g_npts[gv];
        float ax = (float)(v & (G - 1)) + vs * 0.5f;
        float ay = (float)(v >> (8 - s)) + vs * 0.5f;
        for (int k = 0; k < KCAP; k++) {
            int idx = g_slots[gv * KCAP + k];
            if (idx == SENT) continue;
            float a  = __ldg(&pts[idx * 5 + 0]);
            float b  = __ldg(&pts[idx * 5 + 1]);
            float zc = __ldg(&pts[idx * 5 + 2]);
            float f0 = __ldg(&pts[idx * 5 + 3]);
            float f1 = __ldg(&pts[idx * 5 + 4]);
            float x[XD];
            x[0] = f0; x[1] = f1;
            x[2] = a - ax; x[3] = b - ay; x[4] = zc - 4.0f;
            x[5] = a - cx; x[6] = b - cy; x[7] = zc - cz;
            x[8] = cx; x[9] = cy; x[10] = cz; x[11] = n;
            float y = bp;
            #pragma unroll
            for (int q2 = 0; q2 < XD; q2++) y += x[q2] * sw[q2 * OC + c];
            y = (y - ym) * al + be;
            y = fmaxf(y, 0.f);
            float dx = x[2], dy = x[3], dz = x[4];
            #pragma unroll
            for (int q = 0; q < NKP; q++) {
                float ex = dx - skp[q * 3 + 0];
                float ey = dy - skp[q * 3 + 1];
                float ez = dz - skp[q * 3 + 2];
                float d2 = ex * ex + ey * ey + ez * ez;
                float h = 1.0f - sqrtf(d2 + 1e-12f);
                if (h > 0.f) { sreg[q] += h * y; kmask |= (1u << q); }
            }
        }
        #pragma unroll
        for (int q = 0; q < NKP; q++) ss[q * OC + c] = sreg[q];
        __syncthreads();
        float acc = 0.f;
        for (int q = 0; q < NKP; q++) {
            if (!((kmask >> q) & 1)) continue;
            #pragma unroll 8
            for (int c2 = 0; c2 < OC; c2++)
                acc += ss[q * OC + c2] * __ldg(&kpw[(q * OC + c2) * OC + c]);
        }
        g_out[(size_t)(voff + i) * OC + c] = acc;
    }
}

// ---------------- kernel 6: S1 / S2 over active outs, all scales, ILP-4 ----------------
__global__ void k_poststats() {
    int s = blockIdx.y;
    int t = blockIdx.x * blockDim.x + threadIdx.x;
    int n = g_nactive[s];
    size_t obase = (size_t)c_VOFF[s] * OC;
    if (t < OC * OC) {
        int c1 = t >> 6, c2 = t & 63;
        double s0 = 0, s1 = 0, s2 = 0, s3 = 0;
        int i = 0;
        for (; i + 4 <= n; i += 4) {
            s0 += (double)g_out[obase + (size_t)(i + 0) * OC + c1] * (double)g_out[obase + (size_t)(i + 0) * OC + c2];
            s1 += (double)g_out[obase + (size_t)(i + 1) * OC + c1] * (double)g_out[obase + (size_t)(i + 1) * OC + c2];
            s2 += (double)g_out[obase + (size_t)(i + 2) * OC + c1] * (double)g_out[obase + (size_t)(i + 2) * OC + c2];
            s3 += (double)g_out[obase + (size_t)(i + 3) * OC + c1] * (double)g_out[obase + (size_t)(i + 3) * OC + c2];
        }
        for (; i < n; i++)
            s0 += (double)g_out[obase + (size_t)i * OC + c1] * (double)g_out[obase + (size_t)i * OC + c2];
        g_S2[s * OC * OC + t] = (s0 + s1) + (s2 + s3);
    } else if (t < OC * OC + OC) {
        int cc = t - OC * OC;
        double s0 = 0;
        for (int i = 0; i < n; i++) s0 += (double)g_out[obase + (size_t)i * OC + cc];
        g_S1[s * OC + cc] = s0;
    }
}

// ---------------- kernel 7: post-BN finalize, smem-staged weight column ----------------
__global__ void __launch_bounds__(256) k_postfin(
        const float* __restrict__ w_post, const float* __restrict__ b_post,
        const float* __restrict__ g_post, const float* __restrict__ be_post) {
    __shared__ double swc[OC];
    __shared__ double sq[8], sm1[8];
    int s = blockIdx.y;
    int c = blockIdx.x, t = threadIdx.x, lane = t & 31, w = t >> 5;
    if (t < OC) swc[t] = (double)w_post[t * OC + c];   // one strided load set per block
    __syncthreads();
    const double* S2 = &g_S2[s * OC * OC];
    double q_p = 0;
    #pragma unroll
    for (int r = 0; r < 16; r++) {
        int m = t + r * 256;                // coalesced S2 reads; weights from SMEM
        int a = m >> 6, b = m & 63;
        q_p += swc[a] * S2[m] * swc[b];
    }
    double m1_p = (t < OC) ? g_S1[s * OC + t] * swc[t] : 0.0;
    #pragma unroll
    for (int o = 16; o; o >>= 1) {
        q_p  += __shfl_xor_sync(0xffffffffu, q_p, o);
        m1_p += __shfl_xor_sync(0xffffffffu, m1_p, o);
    }
    if (lane == 0) { sq[w] = q_p; sm1[w] = m1_p; }
    __syncthreads();
    if (t == 0) {
        double q = 0, m1 = 0;
        #pragma unroll
        for (int i = 0; i < 8; i++) { q += sq[i]; m1 += sm1[i]; }
        int V = (256 >> s) * (256 >> s);
        double bb = (double)b_post[c];
        double Vd = (double)V;
        double mean = m1 / Vd + bb;
        double Ez2 = (q + 2.0 * bb * m1) / Vd + bb * bb;
        double var = Ez2 - mean * mean;
        if (var < 0) var = 0;
        double alpha = (double)g_post[c] / sqrt(var + 1e-5);
        g_pmean[s * OC + c]  = (float)mean;
        g_palpha[s * OC + c] = (float)alpha;
        float fill = (float)((bb - mean) * alpha + (double)be_post[c]);
        g_fill[s * OC + c] = fmaxf(fill, 0.f);
    }
}

// ---------------- kernel 8: fill whole output (all scales), vectorized ----------------
__global__ void k_fill4(float4* __restrict__ out4) {
    int e = blockIdx.x * blockDim.x + threadIdx.x;     // float4 units, total 1,392,640
    if (e >= 1392640) return;
    int s, off, sh;
    if (e < 1048576)       { s = 0; off = 0;       sh = 14; }
    else if (e < 1310720)  { s = 1; off = 1048576; sh = 12; }
    else if (e < 1376256)  { s = 2; off = 1310720; sh = 10; }
    else                   { s = 3; off = 1376256; sh = 8;  }
    float f = g_fill[s * OC + ((e - off) >> sh)];
    out4[e] = make_float4(f, f, f, f);
}

// ---------------- kernel 9: scatter active-voxel outputs, all scales ----------------
__global__ void __launch_bounds__(64) k_scatter(float* __restrict__ out,
        const float* __restrict__ w_post, const float* __restrict__ b_post,
        const float* __restrict__ be_post) {
    int s = blockIdx.y;
    int c = threadIdx.x;
    int n = g_nactive[s];
    int V = (256 >> s) * (256 >> s);
    size_t outbase = (size_t)OC * c_VOFF[s];   // output-plane offset == OC * cumulative V
    size_t obase   = (size_t)c_VOFF[s] * OC;
    float pm = g_pmean[s * OC + c], pa = g_palpha[s * OC + c], be = be_post[c];
    for (int i = blockIdx.x; i < n; i += gridDim.x) {
        int v = g_active[c_VOFF[s] + i];
        float z = b_post[c];
        #pragma unroll 8
        for (int k = 0; k < OC; k++)
            z += g_out[obase + (size_t)i * OC + k] * __ldg(&w_post[k * OC + c]);
        float zn = fmaxf((z - pm) * pa + be, 0.f);
        out[outbase + (size_t)c * V + v] = zn;
    }
}

// ---------------- launcher ----------------
extern "C" void kernel_launch(void* const* d_in, const int* in_sizes, int n_in,
                              void* d_out, int out_size) {
    const float* pts     = (const float*)d_in[0];
    const float* kp      = (const float*)d_in[1];
    const float* w_pre   = (const float*)d_in[2];
    const float* b_pre   = (const float*)d_in[3];
    const float* g_pre   = (const float*)d_in[4];
    const float* be_pre  = (const float*)d_in[5];
    const float* kpw     = (const float*)d_in[6];
    const float* w_post  = (const float*)d_in[7];
    const float* b_post  = (const float*)d_in[8];
    const float* g_post  = (const float*)d_in[9];
    const float* be_post = (const float*)d_in[10];
    float* out = (float*)d_out;
    int N = in_sizes[0] / 5;

    k_init     <<<(NSLOT_TOT + 255) / 256, 256>>>();
    if (N > 0) k_insert<<<(N + 255) / 256, 256>>>(pts, N);
    k_voxstats <<<NVOX_TOT / 256, 256>>>(pts, kp);
    k_prebn    <<<4, 1024>>>(w_pre, b_pre, g_pre);
    k_activeout<<<dim3(64, 4), 64>>>(pts, kp, kpw, w_pre, b_pre, be_pre);
    k_poststats<<<dim3(17, 4), 256>>>();
    k_postfin  <<<dim3(64, 4), 256>>>(w_post, b_post, g_post, be_post);
    k_fill4    <<<(1392640 + 255) / 256, 256>>>((float4*)out);
    k_scatter  <<<dim3(64, 4), 64>>>(out, w_post, b_post, be_post);
}

// round 13
// speedup vs baseline: 6.6548x; 1.0317x over previous
#include <cuda_runtime.h>
#include <cstdint>

#define KCAP 8
#define NKP 15
#define OC 64
#define XD 12
#define NMOM 91            // cnt(1) + Sx(12) + Sxx upper-tri(78)
#define SENT 0x7FFFFFFF
#define NVOX_TOT 87040     // 65536 + 16384 + 4096 + 1024
#define NSLOT_TOT (NVOX_TOT * KCAP)

// per-scale voxel offsets (cumulative V); also active-list and output-plane offsets
__device__ __constant__ int c_VOFF[5] = {0, 65536, 81920, 86016, 87040};
// upper-triangle (a,b) pairs for XD=12 second moments — __device__ (LDG path, no LDC replay)
__device__ const signed char d_triA[78] = {
    0,0,0,0,0,0,0,0,0,0,0,0, 1,1,1,1,1,1,1,1,1,1,1, 2,2,2,2,2,2,2,2,2,2,
    3,3,3,3,3,3,3,3,3, 4,4,4,4,4,4,4,4, 5,5,5,5,5,5,5, 6,6,6,6,6,6,
    7,7,7,7,7, 8,8,8,8, 9,9,9, 10,10, 11};
__device__ const signed char d_triB[78] = {
    0,1,2,3,4,5,6,7,8,9,10,11, 1,2,3,4,5,6,7,8,9,10,11, 2,3,4,5,6,7,8,9,10,11,
    3,4,5,6,7,8,9,10,11, 4,5,6,7,8,9,10,11, 5,6,7,8,9,10,11, 6,7,8,9,10,11,
    7,8,9,10,11, 8,9,10,11, 9,10,11, 10,11, 11};

// ---------------- device scratch (static, no allocs) ----------------
__device__ int    g_slots[NSLOT_TOT];
__device__ float  g_cent[NVOX_TOT * 3];
__device__ int    g_npts[NVOX_TOT];
__device__ int    g_active[NVOX_TOT];        // per-scale regions at c_VOFF
__device__ int    g_nactive[4];
__device__ double g_mom[4 * 92];             // double accumulate (atomic), read as float
__device__ float  g_ym[4 * OC];
__device__ float  g_apre[4 * OC];
__device__ float  g_S1[4 * OC];              // float: FP64 pipe is 1/64-rate on sm_103a
__device__ float  g_S2[4 * OC * OC];
__device__ float  g_out[(size_t)NVOX_TOT * OC];
__device__ float  g_pmean[4 * OC], g_palpha[4 * OC], g_fill[4 * OC];

// ---------------- kernel 1: init ----------------
__global__ void k_init() {
    int i = blockIdx.x * blockDim.x + threadIdx.x;
    if (i < NSLOT_TOT) g_slots[i] = SENT;
    if (i < 4 * 92) g_mom[i] = 0.0;
    if (i < 4) g_nactive[i] = 0;
}

// ---------------- kernel 2: fused 4-scale insert (first-K by original index) ----------------
__global__ void k_insert(const float* __restrict__ pts, int N) {
    int i = blockIdx.x * blockDim.x + threadIdx.x;
    if (i >= N) return;
    float x = pts[i * 5 + 0], y = pts[i * 5 + 1], z = pts[i * 5 + 2];
    if (!(z >= -5.0f && z < 3.0f)) return;
    float bx = x + 51.2f, by = y + 51.2f;
    int G = 256;
    float vs = 0.4f;
    #pragma unroll
    for (int s = 0; s < 4; s++) {
        float fx = floorf(bx / vs), fy = floorf(by / vs);
        if (fx >= 0.f && fy >= 0.f && fx < (float)G && fy < (float)G) {
            int ix = (int)fx, iy = (int)fy;
            int* sl = &g_slots[(c_VOFF[s] + iy * G + ix) * KCAP];
            int val = i;
            #pragma unroll
            for (int k = 0; k < KCAP; k++) {
                int cur = sl[k];            // racy pre-check OK: slot values only decrease
                if (cur < val) continue;
                int old = atomicMin(&sl[k], val);
                if (old == SENT) break;
                val = max(val, old);
            }
        }
        G >>= 1;
        vs *= 2.0f;
    }
}

// ---------------- kernel 3: all-scale centroid + active detect + moments ----------------
__global__ void __launch_bounds__(256) k_voxstats(
        const float* __restrict__ pts, const float* __restrict__ kp) {
    __shared__ float skp[NKP * 3];
    __shared__ float sAcc[NMOM];
    int t = threadIdx.x, lane = t & 31;
    if (t < NKP * 3) skp[t] = kp[t];
    if (t < NMOM) sAcc[t] = 0.f;
    __syncthreads();

    int gv = blockIdx.x * 256 + t;              // global voxel index (all scales)
    int s = (gv < 65536) ? 0 : (gv < 81920) ? 1 : (gv < 86016) ? 2 : 3;
    int v = gv - c_VOFF[s];
    int G = 256 >> s;
    float vs = 0.4f * (float)(1 << s);
    const int* sl = &g_slots[gv * KCAP];
    float ax = (float)(v & (G - 1)) + vs * 0.5f;
    float ay = (float)(v >> (8 - s)) + vs * 0.5f;

    int idxs[KCAP];
    int cnt = 0;
    float sx = 0.f, sy = 0.f, sz = 0.f;
    bool act = false;
    #pragma unroll
    for (int k = 0; k < KCAP; k++) {
        int idx = sl[k];
        idxs[k] = idx;
        if (idx == SENT) continue;
        float a = __ldg(&pts[idx * 5 + 0]);
        float b = __ldg(&pts[idx * 5 + 1]);
        float c = __ldg(&pts[idx * 5 + 2]);
        sx += a; sy += b; sz += c; cnt++;
        if (!act) {
            float dx = a - ax, dy = b - ay, dz = c - 4.0f;
            #pragma unroll
            for (int q = 0; q < NKP; q++) {
                float ex = dx - skp[q * 3 + 0];
                float ey = dy - skp[q * 3 + 1];
                float ez = dz - skp[q * 3 + 2];
                if (ex * ex + ey * ey + ez * ez < 1.0f) { act = true; break; }
            }
        }
    }
    g_npts[gv] = cnt;
    float nf = (float)max(cnt, 1);
    float cx = sx / nf, cy = sy / nf, cz = sz / nf;
    g_cent[gv * 3 + 0] = cx;
    g_cent[gv * 3 + 1] = cy;
    g_cent[gv * 3 + 2] = cz;
    if (act) { int p = atomicAdd(&g_nactive[s], 1); g_active[c_VOFF[s] + p] = v; }

    float m1[XD];
    float m2[78];
    #pragma unroll
    for (int i2 = 0; i2 < XD; i2++) m1[i2] = 0.f;
    #pragma unroll
    for (int i2 = 0; i2 < 78; i2++) m2[i2] = 0.f;
    float n = (float)cnt;
    #pragma unroll
    for (int k = 0; k < KCAP; k++) {
        int idx = idxs[k];
        if (idx == SENT) continue;
        float a  = __ldg(&pts[idx * 5 + 0]);
        float b  = __ldg(&pts[idx * 5 + 1]);
        float c  = __ldg(&pts[idx * 5 + 2]);
        float f0 = __ldg(&pts[idx * 5 + 3]);
        float f1 = __ldg(&pts[idx * 5 + 4]);
        float x[XD];
        x[0] = f0; x[1] = f1;
        x[2] = a - ax; x[3] = b - ay; x[4] = c - 4.0f;
        x[5] = a - cx; x[6] = b - cy; x[7] = c - cz;
        x[8] = cx; x[9] = cy; x[10] = cz; x[11] = n;
        #pragma unroll
        for (int i2 = 0; i2 < XD; i2++) m1[i2] += x[i2];
        int j = 0;
        #pragma unroll
        for (int a2 = 0; a2 < XD; a2++)
            #pragma unroll
            for (int b2 = a2; b2 < XD; b2++) { m2[j] += x[a2] * x[b2]; j++; }
    }

    {
        float val = (float)cnt;
        #pragma unroll
        for (int o = 16; o; o >>= 1) val += __shfl_xor_sync(0xffffffffu, val, o);
        if (lane == 0) atomicAdd(&sAcc[0], val);
    }
    #pragma unroll
    for (int i2 = 0; i2 < XD; i2++) {
        float val = m1[i2];
        #pragma unroll
        for (int o = 16; o; o >>= 1) val += __shfl_xor_sync(0xffffffffu, val, o);
        if (lane == 0) atomicAdd(&sAcc[1 + i2], val);
    }
    #pragma unroll
    for (int i2 = 0; i2 < 78; i2++) {
        float val = m2[i2];
        #pragma unroll
        for (int o = 16; o; o >>= 1) val += __shfl_xor_sync(0xffffffffu, val, o);
        if (lane == 0) atomicAdd(&sAcc[13 + i2], val);
    }
    __syncthreads();
    if (t < NMOM) atomicAdd(&g_mom[s * 92 + t], (double)sAcc[t]);
}

// ---------------- kernel 4: pre-BN finalize — float wide phase, double tail ----------------
__global__ void __launch_bounds__(1024) k_prebn(
        const float* __restrict__ w_pre, const float* __restrict__ b_pre,
        const float* __restrict__ g_pre) {
    __shared__ float smomf[92];
    __shared__ float swp[XD * OC];
    int s = blockIdx.x;
    int t = threadIdx.x;
    if (t < 92) smomf[t] = (float)g_mom[s * 92 + t];
    if (t < XD * OC) swp[t] = w_pre[t];
    __syncthreads();
    int c = t >> 4, p = t & 15;
    float sxw_p = (p < XD) ? smomf[1 + p] * swp[p * OC + c] : 0.f;
    float q_p = 0.f;
    int j0 = p * 5;
    #pragma unroll
    for (int jj = 0; jj < 5; jj++) {
        int j = j0 + jj;
        if (j < 78) {
            int a = d_triA[j], b = d_triB[j];
            float term = smomf[13 + j] * swp[a * OC + c] * swp[b * OC + c];
            q_p += (a == b) ? term : 2.0f * term;
        }
    }
    #pragma unroll
    for (int o = 8; o; o >>= 1) {
        sxw_p += __shfl_xor_sync(0xffffffffu, sxw_p, o);
        q_p   += __shfl_xor_sync(0xffffffffu, q_p, o);
    }
    if (p == 0) {
        double cnt = (double)smomf[0];
        double den = cnt > 1.0 ? cnt : 1.0;
        double sxw = (double)sxw_p, q = (double)q_p;
        double b = (double)b_pre[c];
        double ym = (sxw + cnt * b) / den;
        double Ey2 = (q + 2.0 * b * sxw + cnt * b * b) / den;
        double var = Ey2 - ym * ym;
        if (var < 0) var = 0;
        g_ym[s * OC + c]   = (float)ym;
        g_apre[s * OC + c] = (float)((double)g_pre[c] / sqrt(var + 1e-5));
    }
}

// ---------------- kernel 5: KP conv + out for active voxels, all scales ----------------
__global__ void __launch_bounds__(64) k_activeout(
        const float* __restrict__ pts, const float* __restrict__ kp,
        const float* __restrict__ kpw, const float* __restrict__ w_pre,
        const float* __restrict__ b_pre, const float* __restrict__ be_pre) {
    __shared__ float sw[XD * OC];
    __shared__ float skp[NKP * 3];
    __shared__ float ss[NKP * OC];
    int s = blockIdx.y;
    int c = threadIdx.x;
    for (int i = c; i < XD * OC; i += 64) sw[i] = w_pre[i];
    if (c < NKP * 3) skp[c] = kp[c];
    int G = 256 >> s;
    float vs = 0.4f * (float)(1 << s);
    int voff = c_VOFF[s];
    float ym = g_ym[s * OC + c], al = g_apre[s * OC + c];
    float be = be_pre[c], bp = b_pre[c];
    int nact = g_nactive[s];
    for (int i = blockIdx.x; i < nact; i += gridDim.x) {
        __syncthreads();
        int v = g_active[voff + i];
        int gv = voff + v;
        float sreg[NKP];
        #pragma unroll
        for (int q = 0; q < NKP; q++) sreg[q] = 0.f;
        unsigned kmask = 0;
        float cx = g_cent[gv * 3 + 0], cy = g_cent[gv * 3 + 1], cz = g_cent[gv * 3 + 2];
        float n  = (float)g_npts[gv];
        float ax = (float)(v & (G - 1)) + vs * 0.5f;
        float ay = (float)(v >> (8 - s)) + vs * 0.5f;
        for (int k = 0; k < KCAP; k++) {
            int idx = g_slots[gv * KCAP + k];
            if (idx == SENT) continue;
            float a  = __ldg(&pts[idx * 5 + 0]);
            float b  = __ldg(&pts[idx * 5 + 1]);
            float zc = __ldg(&pts[idx * 5 + 2]);
            float f0 = __ldg(&pts[idx * 5 + 3]);
            float f1 = __ldg(&pts[idx * 5 + 4]);
            float x[XD];
            x[0] = f0; x[1] = f1;
            x[2] = a - ax; x[3] = b - ay; x[4] = zc - 4.0f;
            x[5] = a - cx; x[6] = b - cy; x[7] = zc - cz;
            x[8] = cx; x[9] = cy; x[10] = cz; x[11] = n;
            float y = bp;
            #pragma unroll
            for (int q2 = 0; q2 < XD; q2++) y += x[q2] * sw[q2 * OC + c];
            y = (y - ym) * al + be;
            y = fmaxf(y, 0.f);
            float dx = x[2], dy = x[3], dz = x[4];
            #pragma unroll
            for (int q = 0; q < NKP; q++) {
                float ex = dx - skp[q * 3 + 0];
                float ey = dy - skp[q * 3 + 1];
                float ez = dz - skp[q * 3 + 2];
                float d2 = ex * ex + ey * ey + ez * ez;
                float h = 1.0f - sqrtf(d2 + 1e-12f);
                if (h > 0.f) { sreg[q] += h * y; kmask |= (1u << q); }
            }
        }
        #pragma unroll
        for (int q = 0; q < NKP; q++) ss[q * OC + c] = sreg[q];
        __syncthreads();
        float acc = 0.f;
        for (int q = 0; q < NKP; q++) {
            if (!((kmask >> q) & 1)) continue;
            #pragma unroll 8
            for (int c2 = 0; c2 < OC; c2++)
                acc += ss[q * OC + c2] * __ldg(&kpw[(q * OC + c2) * OC + c]);
        }
        g_out[(size_t)(voff + i) * OC + c] = acc;
    }
}

// ---------------- kernel 6: S1 / S2 over active outs — float, ILP-8 ----------------
__global__ void k_poststats() {
    int s = blockIdx.y;
    int t = blockIdx.x * blockDim.x + threadIdx.x;
    int n = g_nactive[s];
    size_t obase = (size_t)c_VOFF[s] * OC;
    if (t < OC * OC) {
        int c1 = t >> 6, c2 = t & 63;
        float acc[8];
        #pragma unroll
        for (int u = 0; u < 8; u++) acc[u] = 0.f;
        int i = 0;
        for (; i + 8 <= n; i += 8) {
            #pragma unroll
            for (int u = 0; u < 8; u++)
                acc[u] += g_out[obase + (size_t)(i + u) * OC + c1] *
                          g_out[obase + (size_t)(i + u) * OC + c2];
        }
        for (; i < n; i++)
            acc[0] += g_out[obase + (size_t)i * OC + c1] * g_out[obase + (size_t)i * OC + c2];
        g_S2[s * OC * OC + t] = ((acc[0] + acc[1]) + (acc[2] + acc[3])) +
                                ((acc[4] + acc[5]) + (acc[6] + acc[7]));
    } else if (t < OC * OC + OC) {
        int cc = t - OC * OC;
        float s0 = 0.f, s1 = 0.f, s2 = 0.f, s3 = 0.f;
        int i = 0;
        for (; i + 4 <= n; i += 4) {
            s0 += g_out[obase + (size_t)(i + 0) * OC + cc];
            s1 += g_out[obase + (size_t)(i + 1) * OC + cc];
            s2 += g_out[obase + (size_t)(i + 2) * OC + cc];
            s3 += g_out[obase + (size_t)(i + 3) * OC + cc];
        }
        for (; i < n; i++) s0 += g_out[obase + (size_t)i * OC + cc];
        g_S1[s * OC + cc] = (s0 + s1) + (s2 + s3);
    }
}

// ---------------- kernel 7: post-BN finalize — float wide phase, double tail ----------------
__global__ void __launch_bounds__(256) k_postfin(
        const float* __restrict__ w_post, const float* __restrict__ b_post,
        const float* __restrict__ g_post, const float* __restrict__ be_post) {
    __shared__ float swc[OC];
    __shared__ float sq[8], sm1[8];
    int s = blockIdx.y;
    int c = blockIdx.x, t = threadIdx.x, lane = t & 31, w = t >> 5;
    if (t < OC) swc[t] = w_post[t * OC + c];
    __syncthreads();
    const float* S2 = &g_S2[s * OC * OC];
    float q_p = 0.f;
    #pragma unroll
    for (int r = 0; r < 16; r++) {
        int m = t + r * 256;                // coalesced S2 reads; weights from SMEM
        int a = m >> 6, b = m & 63;
        q_p += swc[a] * S2[m] * swc[b];
    }
    float m1_p = (t < OC) ? g_S1[s * OC + t] * swc[t] : 0.f;
    #pragma unroll
    for (int o = 16; o; o >>= 1) {
        q_p  += __shfl_xor_sync(0xffffffffu, q_p, o);
        m1_p += __shfl_xor_sync(0xffffffffu, m1_p, o);
    }
    if (lane == 0) { sq[w] = q_p; sm1[w] = m1_p; }
    __syncthreads();
    if (t == 0) {
        float qf = 0.f, m1f = 0.f;
        #pragma unroll
        for (int i = 0; i < 8; i++) { qf += sq[i]; m1f += sm1[i]; }
        double q = (double)qf, m1 = (double)m1f;
        int V = (256 >> s) * (256 >> s);
        double bb = (double)b_post[c];
        double Vd = (double)V;
        double mean = m1 / Vd + bb;
        double Ez2 = (q + 2.0 * bb * m1) / Vd + bb * bb;
        double var = Ez2 - mean * mean;
        if (var < 0) var = 0;
        double alpha = (double)g_post[c] / sqrt(var + 1e-5);
        g_pmean[s * OC + c]  = (float)mean;
        g_palpha[s * OC + c] = (float)alpha;
        float fill = (float)((bb - mean) * alpha + (double)be_post[c]);
        g_fill[s * OC + c] = fmaxf(fill, 0.f);
    }
}

// ---------------- kernel 8: fill whole output (all scales), vectorized ----------------
__global__ void k_fill4(float4* __restrict__ out4) {
    int e = blockIdx.x * blockDim.x + threadIdx.x;     // float4 units, total 1,392,640
    if (e >= 1392640) return;
    int s, off, sh;
    if (e < 1048576)       { s = 0; off = 0;       sh = 14; }
    else if (e < 1310720)  { s = 1; off = 1048576; sh = 12; }
    else if (e < 1376256)  { s = 2; off = 1310720; sh = 10; }
    else                   { s = 3; off = 1376256; sh = 8;  }
    float f = g_fill[s * OC + ((e - off) >> sh)];
    out4[e] = make_float4(f, f, f, f);
}

// ---------------- kernel 9: scatter active-voxel outputs, all scales ----------------
__global__ void __launch_bounds__(64) k_scatter(float* __restrict__ out,
        const float* __restrict__ w_post, const float* __restrict__ b_post,
        const float* __restrict__ be_post) {
    int s = blockIdx.y;
    int c = threadIdx.x;
    int n = g_nactive[s];
    int V = (256 >> s) * (256 >> s);
    size_t outbase = (size_t)OC * c_VOFF[s];   // output-plane offset == OC * cumulative V
    size_t obase   = (size_t)c_VOFF[s] * OC;
    float pm = g_pmean[s * OC + c], pa = g_palpha[s * OC + c], be = be_post[c];
    for (int i = blockIdx.x; i < n; i += gridDim.x) {
        int v = g_active[c_VOFF[s] + i];
        float z = b_post[c];
        #pragma unroll 8
        for (int k = 0; k < OC; k++)
            z += g_out[obase + (size_t)i * OC + k] * __ldg(&w_post[k * OC + c]);
        float zn = fmaxf((z - pm) * pa + be, 0.f);
        out[outbase + (size_t)c * V + v] = zn;
    }
}

// ---------------- launcher ----------------
extern "C" void kernel_launch(void* const* d_in, const int* in_sizes, int n_in,
                              void* d_out, int out_size) {
    const float* pts     = (const float*)d_in[0];
    const float* kp      = (const float*)d_in[1];
    const float* w_pre   = (const float*)d_in[2];
    const float* b_pre   = (const float*)d_in[3];
    const float* g_pre   = (const float*)d_in[4];
    const float* be_pre  = (const float*)d_in[5];
    const float* kpw     = (const float*)d_in[6];
    const float* w_post  = (const float*)d_in[7];
    const float* b_post  = (const float*)d_in[8];
    const float* g_post  = (const float*)d_in[9];
    const float* be_post = (const float*)d_in[10];
    float* out = (float*)d_out;
    int N = in_sizes[0] / 5;

    k_init     <<<(NSLOT_TOT + 255) / 256, 256>>>();
    if (N > 0) k_insert<<<(N + 255) / 256, 256>>>(pts, N);
    k_voxstats <<<NVOX_TOT / 256, 256>>>(pts, kp);
    k_prebn    <<<4, 1024>>>(w_pre, b_pre, g_pre);
    k_activeout<<<dim3(64, 4), 64>>>(pts, kp, kpw, w_pre, b_pre, be_pre);
    k_poststats<<<dim3(17, 4), 256>>>();
    k_postfin  <<<dim3(64, 4), 256>>>(w_post, b_post, g_post, be_post);
    k_fill4    <<<(1392640 + 255) / 256, 256>>>((float4*)out);
    k_scatter  <<<dim3(64, 4), 64>>>(out, w_post, b_post, be_post);
}

// round 14
// speedup vs baseline: 7.3652x; 1.1067x over previous
#include <cuda_runtime.h>
#include <cstdint>

#define KCAP 8
#define NKP 15
#define OC 64
#define XD 12
#define NMOM 91            // cnt(1) + Sx(12) + Sxx upper-tri(78)
#define SENT 0x7FFFFFFF
#define NVOX_TOT 87040     // 65536 + 16384 + 4096 + 1024
#define NSLOT_TOT (NVOX_TOT * KCAP)

// per-scale voxel offsets (cumulative V); also active-list and output-plane offsets
__device__ __constant__ int c_VOFF[5] = {0, 65536, 81920, 86016, 87040};
// upper-triangle (a,b) pairs for XD=12 second moments — __device__ (LDG path)
__device__ const signed char d_triA[78] = {
    0,0,0,0,0,0,0,0,0,0,0,0, 1,1,1,1,1,1,1,1,1,1,1, 2,2,2,2,2,2,2,2,2,2,
    3,3,3,3,3,3,3,3,3, 4,4,4,4,4,4,4,4, 5,5,5,5,5,5,5, 6,6,6,6,6,6,
    7,7,7,7,7, 8,8,8,8, 9,9,9, 10,10, 11};
__device__ const signed char d_triB[78] = {
    0,1,2,3,4,5,6,7,8,9,10,11, 1,2,3,4,5,6,7,8,9,10,11, 2,3,4,5,6,7,8,9,10,11,
    3,4,5,6,7,8,9,10,11, 4,5,6,7,8,9,10,11, 5,6,7,8,9,10,11, 6,7,8,9,10,11,
    7,8,9,10,11, 8,9,10,11, 9,10,11, 10,11, 11};

// ---------------- device scratch (static, no allocs) ----------------
__device__ int    g_slots[NSLOT_TOT];
__device__ float  g_cent[NVOX_TOT * 3];
__device__ int    g_npts[NVOX_TOT];
__device__ int    g_active[NVOX_TOT];        // per-scale regions at c_VOFF
__device__ int    g_actidx[NVOX_TOT];        // -1 or active-list position
__device__ int    g_nactive[4];
__device__ double g_mom[4 * 92];             // double atomic accumulate
__device__ float  g_out[(size_t)NVOX_TOT * OC];   // KP-conv outputs
__device__ float  g_zval[(size_t)NVOX_TOT * OC];  // final normalized z (active voxels)
__device__ float  g_fill[4 * OC];

// ---------------- kernel 1: init ----------------
__global__ void k_init() {
    int i = blockIdx.x * blockDim.x + threadIdx.x;
    if (i < NSLOT_TOT) g_slots[i] = SENT;
    if (i < NVOX_TOT) g_actidx[i] = -1;
    if (i < 4 * 92) g_mom[i] = 0.0;
    if (i < 4) g_nactive[i] = 0;
}

// ---------------- kernel 2: fused 4-scale insert (first-K by original index) ----------------
__global__ void k_insert(const float* __restrict__ pts, int N) {
    int i = blockIdx.x * blockDim.x + threadIdx.x;
    if (i >= N) return;
    float x = pts[i * 5 + 0], y = pts[i * 5 + 1], z = pts[i * 5 + 2];
    if (!(z >= -5.0f && z < 3.0f)) return;
    float bx = x + 51.2f, by = y + 51.2f;
    int G = 256;
    float vs = 0.4f;
    #pragma unroll
    for (int s = 0; s < 4; s++) {
        float fx = floorf(bx / vs), fy = floorf(by / vs);
        if (fx >= 0.f && fy >= 0.f && fx < (float)G && fy < (float)G) {
            int ix = (int)fx, iy = (int)fy;
            int* sl = &g_slots[(c_VOFF[s] + iy * G + ix) * KCAP];
            int val = i;
            #pragma unroll
            for (int k = 0; k < KCAP; k++) {
                int cur = sl[k];            // racy pre-check OK: slot values only decrease
                if (cur < val) continue;
                int old = atomicMin(&sl[k], val);
                if (old == SENT) break;
                val = max(val, old);
            }
        }
        G >>= 1;
        vs *= 2.0f;
    }
}

// ---------------- kernel 3: all-scale centroid + active detect + moments ----------------
__global__ void __launch_bounds__(256) k_voxstats(
        const float* __restrict__ pts, const float* __restrict__ kp) {
    __shared__ float skp[NKP * 3];
    __shared__ float sAcc[NMOM];
    int t = threadIdx.x, lane = t & 31;
    if (t < NKP * 3) skp[t] = kp[t];
    if (t < NMOM) sAcc[t] = 0.f;
    __syncthreads();

    int gv = blockIdx.x * 256 + t;              // global voxel index (all scales)
    int s = (gv < 65536) ? 0 : (gv < 81920) ? 1 : (gv < 86016) ? 2 : 3;
    int v = gv - c_VOFF[s];
    int G = 256 >> s;
    float vs = 0.4f * (float)(1 << s);
    const int* sl = &g_slots[gv * KCAP];
    float ax = (float)(v & (G - 1)) + vs * 0.5f;
    float ay = (float)(v >> (8 - s)) + vs * 0.5f;

    int idxs[KCAP];
    int cnt = 0;
    float sx = 0.f, sy = 0.f, sz = 0.f;
    bool act = false;
    #pragma unroll
    for (int k = 0; k < KCAP; k++) {
        int idx = sl[k];
        idxs[k] = idx;
        if (idx == SENT) continue;
        float a = __ldg(&pts[idx * 5 + 0]);
        float b = __ldg(&pts[idx * 5 + 1]);
        float c = __ldg(&pts[idx * 5 + 2]);
        sx += a; sy += b; sz += c; cnt++;
        if (!act) {
            float dx = a - ax, dy = b - ay, dz = c - 4.0f;
            #pragma unroll
            for (int q = 0; q < NKP; q++) {
                float ex = dx - skp[q * 3 + 0];
                float ey = dy - skp[q * 3 + 1];
                float ez = dz - skp[q * 3 + 2];
                if (ex * ex + ey * ey + ez * ez < 1.0f) { act = true; break; }
            }
        }
    }
    g_npts[gv] = cnt;
    float nf = (float)max(cnt, 1);
    float cx = sx / nf, cy = sy / nf, cz = sz / nf;
    g_cent[gv * 3 + 0] = cx;
    g_cent[gv * 3 + 1] = cy;
    g_cent[gv * 3 + 2] = cz;
    if (act) {
        int p = atomicAdd(&g_nactive[s], 1);
        g_active[c_VOFF[s] + p] = v;
        g_actidx[gv] = p;
    }

    float m1[XD];
    float m2[78];
    #pragma unroll
    for (int i2 = 0; i2 < XD; i2++) m1[i2] = 0.f;
    #pragma unroll
    for (int i2 = 0; i2 < 78; i2++) m2[i2] = 0.f;
    float n = (float)cnt;
    #pragma unroll
    for (int k = 0; k < KCAP; k++) {
        int idx = idxs[k];
        if (idx == SENT) continue;
        float a  = __ldg(&pts[idx * 5 + 0]);
        float b  = __ldg(&pts[idx * 5 + 1]);
        float c  = __ldg(&pts[idx * 5 + 2]);
        float f0 = __ldg(&pts[idx * 5 + 3]);
        float f1 = __ldg(&pts[idx * 5 + 4]);
        float x[XD];
        x[0] = f0; x[1] = f1;
        x[2] = a - ax; x[3] = b - ay; x[4] = c - 4.0f;
        x[5] = a - cx; x[6] = b - cy; x[7] = c - cz;
        x[8] = cx; x[9] = cy; x[10] = cz; x[11] = n;
        #pragma unroll
        for (int i2 = 0; i2 < XD; i2++) m1[i2] += x[i2];
        int j = 0;
        #pragma unroll
        for (int a2 = 0; a2 < XD; a2++)
            #pragma unroll
            for (int b2 = a2; b2 < XD; b2++) { m2[j] += x[a2] * x[b2]; j++; }
    }

    {
        float val = (float)cnt;
        #pragma unroll
        for (int o = 16; o; o >>= 1) val += __shfl_xor_sync(0xffffffffu, val, o);
        if (lane == 0) atomicAdd(&sAcc[0], val);
    }
    #pragma unroll
    for (int i2 = 0; i2 < XD; i2++) {
        float val = m1[i2];
        #pragma unroll
        for (int o = 16; o; o >>= 1) val += __shfl_xor_sync(0xffffffffu, val, o);
        if (lane == 0) atomicAdd(&sAcc[1 + i2], val);
    }
    #pragma unroll
    for (int i2 = 0; i2 < 78; i2++) {
        float val = m2[i2];
        #pragma unroll
        for (int o = 16; o; o >>= 1) val += __shfl_xor_sync(0xffffffffu, val, o);
        if (lane == 0) atomicAdd(&sAcc[13 + i2], val);
    }
    __syncthreads();
    if (t < NMOM) atomicAdd(&g_mom[s * 92 + t], (double)sAcc[t]);
}

// ---------------- kernel 4: activeout with inline per-channel pre-BN ----------------
__global__ void __launch_bounds__(64) k_activeout(
        const float* __restrict__ pts, const float* __restrict__ kp,
        const float* __restrict__ kpw, const float* __restrict__ w_pre,
        const float* __restrict__ b_pre, const float* __restrict__ g_pre,
        const float* __restrict__ be_pre) {
    __shared__ float sw[XD * OC];
    __shared__ float skp[NKP * 3];
    __shared__ float ss[NKP * OC];
    int s = blockIdx.y;
    int c = threadIdx.x;
    for (int i = c; i < XD * OC; i += 64) sw[i] = w_pre[i];
    if (c < NKP * 3) skp[c] = kp[c];
    __syncthreads();

    // inline pre-BN: each thread computes its channel's (ym, al)
    float be = be_pre[c], bp = b_pre[c];
    float ym, al;
    {
        const double* mom = &g_mom[s * 92];
        float cntf = (float)mom[0];
        float sxw = 0.f;
        #pragma unroll
        for (int i = 0; i < XD; i++) sxw += (float)mom[1 + i] * sw[i * OC + c];
        float q = 0.f;
        for (int j = 0; j < 78; j++) {
            int a = d_triA[j], b = d_triB[j];          // uniform loads (broadcast)
            float term = (float)mom[13 + j] * sw[a * OC + c] * sw[b * OC + c];
            q += (a == b) ? term : 2.0f * term;
        }
        double cnt = (double)cntf;
        double den = cnt > 1.0 ? cnt : 1.0;
        double b = (double)bp;
        double ymd = ((double)sxw + cnt * b) / den;
        double Ey2 = ((double)q + 2.0 * b * (double)sxw + cnt * b * b) / den;
        double var = Ey2 - ymd * ymd;
        if (var < 0) var = 0;
        ym = (float)ymd;
        al = (float)((double)g_pre[c] / sqrt(var + 1e-5));
    }

    int G = 256 >> s;
    float vs = 0.4f * (float)(1 << s);
    int voff = c_VOFF[s];
    int nact = g_nactive[s];
    for (int i = blockIdx.x; i < nact; i += gridDim.x) {
        __syncthreads();
        int v = g_active[voff + i];
        int gv = voff + v;
        float sreg[NKP];
        #pragma unroll
        for (int q = 0; q < NKP; q++) sreg[q] = 0.f;
        unsigned kmask = 0;
        float cx = g_cent[gv * 3 + 0], cy = g_cent[gv * 3 + 1], cz = g_cent[gv * 3 + 2];
        float n  = (float)g_npts[gv];
        float ax = (float)(v & (G - 1)) + vs * 0.5f;
        float ay = (float)(v >> (8 - s)) + vs * 0.5f;
        for (int k = 0; k < KCAP; k++) {
            int idx = g_slots[gv * KCAP + k];
            if (idx == SENT) continue;
            float a  = __ldg(&pts[idx * 5 + 0]);
            float b  = __ldg(&pts[idx * 5 + 1]);
            float zc = __ldg(&pts[idx * 5 + 2]);
            float f0 = __ldg(&pts[idx * 5 + 3]);
            float f1 = __ldg(&pts[idx * 5 + 4]);
            float x[XD];
            x[0] = f0; x[1] = f1;
            x[2] = a - ax; x[3] = b - ay; x[4] = zc - 4.0f;
            x[5] = a - cx; x[6] = b - cy; x[7] = zc - cz;
            x[8] = cx; x[9] = cy; x[10] = cz; x[11] = n;
            float y = bp;
            #pragma unroll
            for (int q2 = 0; q2 < XD; q2++) y += x[q2] * sw[q2 * OC + c];
            y = (y - ym) * al + be;
            y = fmaxf(y, 0.f);
            float dx = x[2], dy = x[3], dz = x[4];
            #pragma unroll
            for (int q = 0; q < NKP; q++) {
                float ex = dx - skp[q * 3 + 0];
                float ey = dy - skp[q * 3 + 1];
                float ez = dz - skp[q * 3 + 2];
                float d2 = ex * ex + ey * ey + ez * ez;
                float h = 1.0f - sqrtf(d2 + 1e-12f);
                if (h > 0.f) { sreg[q] += h * y; kmask |= (1u << q); }
            }
        }
        #pragma unroll
        for (int q = 0; q < NKP; q++) ss[q * OC + c] = sreg[q];
        __syncthreads();
        float acc = 0.f;
        for (int q = 0; q < NKP; q++) {
            if (!((kmask >> q) & 1)) continue;
            #pragma unroll 8
            for (int c2 = 0; c2 < OC; c2++)
                acc += ss[q * OC + c2] * __ldg(&kpw[(q * OC + c2) * OC + c]);
        }
        g_out[(size_t)(voff + i) * OC + c] = acc;
    }
}

// ---------------- kernel 5: fused post stats + finalize + z values ----------------
// 4 blocks (one per scale) x 64 threads (one per channel); nactive is tiny.
__global__ void __launch_bounds__(64) k_fusedpost(
        const float* __restrict__ w_post, const float* __restrict__ b_post,
        const float* __restrict__ g_post, const float* __restrict__ be_post) {
    int s = blockIdx.x;
    int c = threadIdx.x;
    int n = g_nactive[s];
    int voff = c_VOFF[s];
    int V = (256 >> s) * (256 >> s);
    float m1 = 0.f, q = 0.f;
    for (int i = 0; i < n; i++) {
        const float* row = &g_out[(size_t)(voff + i) * OC];
        float dot = 0.f;
        #pragma unroll 8
        for (int k = 0; k < OC; k++) dot += row[k] * __ldg(&w_post[k * OC + c]);
        m1 += dot;
        q  += dot * dot;
    }
    double bb = (double)b_post[c];
    double Vd = (double)V;
    double mean = (double)m1 / Vd + bb;
    double Ez2 = ((double)q + 2.0 * bb * (double)m1) / Vd + bb * bb;
    double var = Ez2 - mean * mean;
    if (var < 0) var = 0;
    double alpha = (double)g_post[c] / sqrt(var + 1e-5);
    float pm = (float)mean, pa = (float)alpha, be = be_post[c];
    g_fill[s * OC + c] = fmaxf((float)((bb - mean) * alpha + (double)be), 0.f);
    for (int i = 0; i < n; i++) {
        const float* row = &g_out[(size_t)(voff + i) * OC];
        float dot = 0.f;
        #pragma unroll 8
        for (int k = 0; k < OC; k++) dot += row[k] * __ldg(&w_post[k * OC + c]);
        float z = dot + (float)bb;
        g_zval[(size_t)(voff + i) * OC + c] = fmaxf((z - pm) * pa + be, 0.f);
    }
}

// ---------------- kernel 6: fill + scatter in one pass (vectorized) ----------------
__global__ void k_fillscatter(float4* __restrict__ out4) {
    int e = blockIdx.x * blockDim.x + threadIdx.x;     // float4 units, total 1,392,640
    if (e >= 1392640) return;
    int s, off, sh;
    if (e < 1048576)       { s = 0; off = 0;       sh = 14; }
    else if (e < 1310720)  { s = 1; off = 1048576; sh = 12; }
    else if (e < 1376256)  { s = 2; off = 1310720; sh = 10; }
    else                   { s = 3; off = 1376256; sh = 8;  }
    int rel = e - off;
    int c = rel >> sh;
    int v = (rel & ((1 << sh) - 1)) << 2;              // first of 4 voxels
    int gv = c_VOFF[s] + v;
    float f = g_fill[s * OC + c];
    float4 val = make_float4(f, f, f, f);
    int4 ai = *reinterpret_cast<const int4*>(&g_actidx[gv]);   // gv % 4 == 0: aligned
    if (ai.x >= 0 || ai.y >= 0 || ai.z >= 0 || ai.w >= 0) {    // rare path
        size_t zb = (size_t)c_VOFF[s] * OC + c;
        if (ai.x >= 0) val.x = g_zval[zb + (size_t)ai.x * OC];
        if (ai.y >= 0) val.y = g_zval[zb + (size_t)ai.y * OC];
        if (ai.z >= 0) val.z = g_zval[zb + (size_t)ai.z * OC];
        if (ai.w >= 0) val.w = g_zval[zb + (size_t)ai.w * OC];
    }
    out4[e] = val;
}

// ---------------- launcher ----------------
extern "C" void kernel_launch(void* const* d_in, const int* in_sizes, int n_in,
                              void* d_out, int out_size) {
    const float* pts     = (const float*)d_in[0];
    const float* kp      = (const float*)d_in[1];
    const float* w_pre   = (const float*)d_in[2];
    const float* b_pre   = (const float*)d_in[3];
    const float* g_pre   = (const float*)d_in[4];
    const float* be_pre  = (const float*)d_in[5];
    const float* kpw     = (const float*)d_in[6];
    const float* w_post  = (const float*)d_in[7];
    const float* b_post  = (const float*)d_in[8];
    const float* g_post  = (const float*)d_in[9];
    const float* be_post = (const float*)d_in[10];
    float* out = (float*)d_out;
    int N = in_sizes[0] / 5;

    k_init       <<<(NSLOT_TOT + 255) / 256, 256>>>();
    if (N > 0) k_insert<<<(N + 255) / 256, 256>>>(pts, N);
    k_voxstats   <<<NVOX_TOT / 256, 256>>>(pts, kp);
    k_activeout  <<<dim3(64, 4), 64>>>(pts, kp, kpw, w_pre, b_pre, g_pre, be_pre);
    k_fusedpost  <<<4, 64>>>(w_post, b_post, g_post, be_post);
    k_fillscatter<<<(1392640 + 255) / 256, 256>>>((float4*)out);
}